// round 8
// baseline (speedup 1.0000x reference)
#include <cuda_runtime.h>
#include <cuda_bf16.h>
#include <cstdint>

#define Nn 50000
#define Ee 640000
#define Rr 8
#define NT 391                 // row tiles
#define NB (Rr * NT)           // 3128 buckets
typedef __nv_bfloat16 bf16;

// ---------------- scratch ----------------
__device__ float    g_b1[(size_t)Nn * 128];
__device__ float    g_agg[(size_t)Nn * 128];
__device__ bf16     g_Wchi[9 * 128 * 128], g_Wclo[9 * 128 * 128];   // 8 rels + w1
__device__ bf16     g_m1hi[128 * 128], g_m1lo[128 * 128];
__device__ bf16     g_m2hi[128 * 128], g_m2lo[128 * 128];
__device__ uint32_t g_epack[Ee];
__device__ int      g_hist[NB];
__device__ int      g_off[NB + 1];
__device__ int      g_cur[NB];

// ---------------- asm helpers ----------------
__device__ __forceinline__ uint32_t s2u(const void* p) {
    return (uint32_t)__cvta_generic_to_shared(p);
}
__device__ __forceinline__ void cp16z(uint32_t d, const void* s, int sz) {
    asm volatile("cp.async.cg.shared.global [%0],[%1],16,%2;\n" :: "r"(d), "l"(s), "r"(sz));
}
__device__ __forceinline__ void cp_commit() { asm volatile("cp.async.commit_group;\n"); }
template<int N> __device__ __forceinline__ void cp_wait() {
    asm volatile("cp.async.wait_group %0;\n" :: "n"(N));
}
__device__ __forceinline__ void ldsm4(uint32_t a, uint32_t& r0, uint32_t& r1,
                                      uint32_t& r2, uint32_t& r3) {
    asm volatile("ldmatrix.sync.aligned.m8n8.x4.shared.b16 {%0,%1,%2,%3}, [%4];"
                 : "=r"(r0), "=r"(r1), "=r"(r2), "=r"(r3) : "r"(a));
}
__device__ __forceinline__ void ldsm4t(uint32_t a, uint32_t& r0, uint32_t& r1,
                                       uint32_t& r2, uint32_t& r3) {
    asm volatile("ldmatrix.sync.aligned.m8n8.x4.trans.shared.b16 {%0,%1,%2,%3}, [%4];"
                 : "=r"(r0), "=r"(r1), "=r"(r2), "=r"(r3) : "r"(a));
}
__device__ __forceinline__ void mma16816(float& d0, float& d1, float& d2, float& d3,
                                         uint32_t a0, uint32_t a1, uint32_t a2, uint32_t a3,
                                         uint32_t b0, uint32_t b1) {
    asm volatile(
        "mma.sync.aligned.m16n8k16.row.col.f32.bf16.bf16.f32 "
        "{%0,%1,%2,%3}, {%4,%5,%6,%7}, {%8,%9}, {%0,%1,%2,%3};"
        : "+f"(d0), "+f"(d1), "+f"(d2), "+f"(d3)
        : "r"(a0), "r"(a1), "r"(a2), "r"(a3), "r"(b0), "r"(b1));
}

#define A_STRIDE 80
#define A_CHUNK  (128 * A_STRIDE)   // 10240
#define A_SEG    (4 * A_CHUNK)      // 40960
#define B_STRIDE 272
#define B_CHUNK  (32 * B_STRIDE)    // 8704
#define B_SEG    (4 * B_CHUNK)      // 34816
#define B_BUF    (2 * B_SEG)        // 69632 (>= 64KB staging)
#define FUSED_SMEM (2 * A_SEG + 2 * B_BUF)            // 221184
#define MLP_SMEM   (65536 + 2 * A_SEG + 2 * B_SEG)    // 217088

// ================= edge bucketing (sort by (etype, src-tile)) =================
__global__ __launch_bounds__(256) void hist_kernel(
    const int* __restrict__ src, const int* __restrict__ etype, int* __restrict__ hist)
{
    int e = blockIdx.x * 256 + threadIdx.x;
    if (e >= Ee) return;
    atomicAdd(hist + __ldg(etype + e) * NT + (__ldg(src + e) >> 7), 1);
}

__global__ __launch_bounds__(1024) void scan_kernel(
    const int* __restrict__ hist, int* __restrict__ off, int* __restrict__ cur)
{
    __shared__ int ssum[1024];
    const int t = threadIdx.x;
    const int base = t * 4;
    int v[4], s = 0;
#pragma unroll
    for (int i = 0; i < 4; ++i) {
        v[i] = s;
        int idx = base + i;
        s += (idx < NB) ? hist[idx] : 0;
    }
    ssum[t] = s;
    __syncthreads();
    for (int d = 1; d < 1024; d <<= 1) {
        int x = 0;
        if (t >= d) x = ssum[t - d];
        __syncthreads();
        if (t >= d) ssum[t] += x;
        __syncthreads();
    }
    int excl = (t == 0) ? 0 : ssum[t - 1];
#pragma unroll
    for (int i = 0; i < 4; ++i) {
        int idx = base + i;
        if (idx < NB) { int o = excl + v[i]; off[idx] = o; cur[idx] = o; }
    }
    if (t == 1023) off[NB] = ssum[1023];
}

__global__ __launch_bounds__(256) void esort_kernel(
    const int* __restrict__ src, const int* __restrict__ dst,
    const int* __restrict__ etype, int* __restrict__ cur, uint32_t* __restrict__ epack)
{
    int e = blockIdx.x * 256 + threadIdx.x;
    if (e >= Ee) return;
    int s = __ldg(src + e);
    int b = __ldg(etype + e) * NT + (s >> 7);
    int pos = atomicAdd(cur + b, 1);
    epack[pos] = ((uint32_t)__ldg(dst + e) << 7) | (uint32_t)(s & 127);
}

// ================= fused relation GEMM + in-place edge scatter =================
__global__ __launch_bounds__(256, 1) void rgemm_fused(
    const float* __restrict__ X,
    const bf16* __restrict__ Whi, const bf16* __restrict__ Wlo,
    const float* __restrict__ w1_b,
    const uint32_t* __restrict__ epack, const int* __restrict__ off,
    float* __restrict__ agg, float* __restrict__ b1, int n_rows)
{
    extern __shared__ __align__(16) char sm[];
    const uint32_t sA0 = s2u(sm);
    const uint32_t sB0 = sA0 + 2 * A_SEG;

    const int tid = threadIdx.x, lane = tid & 31, wid = tid >> 5;
    const int wm = wid & 1, wn = wid >> 1;
    const int row0 = blockIdx.x * 128;

    // ---- stage fp32 x tile into sB area, split to sA hi/lo ----
    {
        const int r = tid >> 1, h = tid & 1;
        const int gr = row0 + r;
#pragma unroll
        for (int i = 0; i < 16; ++i)
            cp16z(sB0 + r * 512 + h * 256 + i * 16,
                  X + (size_t)gr * 128 + h * 64 + i * 4, gr < n_rows ? 16 : 0);
        cp_commit();
        cp_wait<0>();
        __syncthreads();
#pragma unroll
        for (int j = 0; j < 32; ++j) {
            int col = h * 64 + j * 2;
            float2 v = *(const float2*)(sm + 2 * A_SEG + r * 512 + col * 4);
            bf16 h0 = __float2bfloat16(v.x), h1 = __float2bfloat16(v.y);
            uint32_t o = (col >> 5) * A_CHUNK + r * A_STRIDE + (col & 31) * 2;
            *(__nv_bfloat162*)(sm + o) = __nv_bfloat162(h0, h1);
            *(__nv_bfloat162*)(sm + A_SEG + o) = __nv_bfloat162(
                __float2bfloat16(v.x - __bfloat162float(h0)),
                __float2bfloat16(v.y - __bfloat162float(h1)));
        }
        __syncthreads();
    }

    const int br = tid >> 4, bq = tid & 15;
    auto loadB = [&](int rel, int buf) {
#pragma unroll
        for (int seg = 0; seg < 2; ++seg) {
            const bf16* g = (seg ? Wlo : Whi) + (size_t)rel * 16384;
#pragma unroll
            for (int c = 0; c < 4; ++c) {
                cp16z(sB0 + buf * B_BUF + seg * B_SEG + c * B_CHUNK + br * B_STRIDE + bq * 16,
                      g + (size_t)(c * 32 + br) * 128 + bq * 8, 16);
                cp16z(sB0 + buf * B_BUF + seg * B_SEG + c * B_CHUNK + (br + 16) * B_STRIDE + bq * 16,
                      g + (size_t)(c * 32 + br + 16) * 128 + bq * 8, 16);
            }
        }
    };
    loadB(0, 0);
    cp_commit();

    float acc[4][4][4];
#pragma unroll
    for (int f = 0; f < 4; ++f)
#pragma unroll
        for (int g = 0; g < 4; ++g)
#pragma unroll
            for (int r = 0; r < 4; ++r) acc[f][g][r] = 0.f;

    const int arow = lane & 15, ahalf = lane >> 4;
    const int blrow = lane & 15, bnc = (lane >> 4) * 8;
    const int tr = lane >> 2, tc = (lane & 3) * 2;

    for (int rel = 0; rel < 9; ++rel) {
        const int buf = rel & 1;
        cp_wait<0>();
        __syncthreads();            // also guarantees prior scatter reads of buf done
        if (rel < 8) { loadB(rel + 1, buf ^ 1); cp_commit(); }

        const uint32_t bB = sB0 + buf * B_BUF;
#pragma unroll
        for (int c = 0; c < 4; ++c) {
#pragma unroll
            for (int s = 0; s < 2; ++s) {
                uint32_t ah[4][4], al[4][4], bh[2][4], bl[2][4];
#pragma unroll
                for (int f = 0; f < 4; ++f) {
                    uint32_t aa = sA0 + c * A_CHUNK + (wm * 64 + f * 16 + arow) * A_STRIDE
                                + (s * 2 + ahalf) * 16;
                    ldsm4(aa,         ah[f][0], ah[f][1], ah[f][2], ah[f][3]);
                    ldsm4(aa + A_SEG, al[f][0], al[f][1], al[f][2], al[f][3]);
                }
#pragma unroll
                for (int g = 0; g < 2; ++g) {
                    uint32_t ba = bB + c * B_CHUNK + (s * 16 + blrow) * B_STRIDE
                                + (wn * 32 + g * 16 + bnc) * 2;
                    ldsm4t(ba,         bh[g][0], bh[g][1], bh[g][2], bh[g][3]);
                    ldsm4t(ba + B_SEG, bl[g][0], bl[g][1], bl[g][2], bl[g][3]);
                }
#pragma unroll
                for (int f = 0; f < 4; ++f) {
#pragma unroll
                    for (int g = 0; g < 2; ++g) {
                        mma16816(acc[f][g*2+0][0], acc[f][g*2+0][1], acc[f][g*2+0][2], acc[f][g*2+0][3],
                                 ah[f][0], ah[f][1], ah[f][2], ah[f][3], bh[g][0], bh[g][1]);
                        mma16816(acc[f][g*2+1][0], acc[f][g*2+1][1], acc[f][g*2+1][2], acc[f][g*2+1][3],
                                 ah[f][0], ah[f][1], ah[f][2], ah[f][3], bh[g][2], bh[g][3]);
                        mma16816(acc[f][g*2+0][0], acc[f][g*2+0][1], acc[f][g*2+0][2], acc[f][g*2+0][3],
                                 ah[f][0], ah[f][1], ah[f][2], ah[f][3], bl[g][0], bl[g][1]);
                        mma16816(acc[f][g*2+1][0], acc[f][g*2+1][1], acc[f][g*2+1][2], acc[f][g*2+1][3],
                                 ah[f][0], ah[f][1], ah[f][2], ah[f][3], bl[g][2], bl[g][3]);
                        mma16816(acc[f][g*2+0][0], acc[f][g*2+0][1], acc[f][g*2+0][2], acc[f][g*2+0][3],
                                 al[f][0], al[f][1], al[f][2], al[f][3], bh[g][0], bh[g][1]);
                        mma16816(acc[f][g*2+1][0], acc[f][g*2+1][1], acc[f][g*2+1][2], acc[f][g*2+1][3],
                                 al[f][0], al[f][1], al[f][2], al[f][3], bh[g][2], bh[g][3]);
                    }
                }
            }
        }

        if (rel < 8) {
            // ---- stage fp32 tile into consumed B slot, then scatter bucket edges ----
            __syncthreads();        // all warps done reading buf
            float* stg = (float*)(sm + 2 * A_SEG + (size_t)buf * B_BUF);
#pragma unroll
            for (int f = 0; f < 4; ++f) {
                int r0l = wm * 64 + f * 16 + tr;
                int r1l = r0l + 8;
#pragma unroll
                for (int g = 0; g < 4; ++g) {
                    int col = wn * 32 + g * 8 + tc;
                    *(float2*)(stg + r0l * 128 + col) = make_float2(acc[f][g][0], acc[f][g][1]);
                    *(float2*)(stg + r1l * 128 + col) = make_float2(acc[f][g][2], acc[f][g][3]);
                    acc[f][g][0] = acc[f][g][1] = acc[f][g][2] = acc[f][g][3] = 0.f;
                }
            }
            __syncthreads();
            const int bkt = rel * NT + blockIdx.x;
            const int st = __ldg(off + bkt), en = __ldg(off + bkt + 1);
            const float4* stg4 = (const float4*)stg;
            for (int e = st + wid; e < en; e += 8) {
                uint32_t p = __ldg(epack + e);
                int sl = p & 127;
                int dd = p >> 7;
                float4 v = stg4[sl * 32 + lane];
                float* o = agg + (size_t)dd * 128 + lane * 4;
                asm volatile("red.global.add.v4.f32 [%0], {%1,%2,%3,%4};"
                             :: "l"(o), "f"(v.x), "f"(v.y), "f"(v.z), "f"(v.w) : "memory");
            }
            // next-iteration top-of-loop __syncthreads() fences buf reuse
        } else {
            // ---- w1 GEMM: b1 = x@w1 + bias, straight to global ----
#pragma unroll
            for (int f = 0; f < 4; ++f) {
                int m0 = row0 + wm * 64 + f * 16 + tr;
                int m1 = m0 + 8;
#pragma unroll
                for (int g = 0; g < 4; ++g) {
                    int col = wn * 32 + g * 8 + tc;
                    float bb0 = w1_b[col], bb1 = w1_b[col + 1];
                    if (m0 < n_rows) *(float2*)(b1 + (size_t)m0 * 128 + col) =
                        make_float2(acc[f][g][0] + bb0, acc[f][g][1] + bb1);
                    if (m1 < n_rows) *(float2*)(b1 + (size_t)m1 * 128 + col) =
                        make_float2(acc[f][g][2] + bb0, acc[f][g][3] + bb1);
                }
            }
        }
    }
}

// ================= fused MLP: out = relu((b1+agg)@m1+b)@m2+b =================
__global__ __launch_bounds__(256, 1) void mlp_fused(
    const float* __restrict__ B1, const float* __restrict__ AGG,
    const bf16* __restrict__ M1hi, const bf16* __restrict__ M1lo,
    const bf16* __restrict__ M2hi, const bf16* __restrict__ M2lo,
    const float* __restrict__ m1_b, const float* __restrict__ m2_b,
    float* __restrict__ out, int n_rows)
{
    extern __shared__ __align__(16) char sm[];
    const uint32_t sStage = s2u(sm);
    const uint32_t sA0 = sStage + 65536;
    const uint32_t sB0 = sA0 + 2 * A_SEG;

    const int tid = threadIdx.x, lane = tid & 31, wid = tid >> 5;
    const int wm = wid & 1, wn = wid >> 1;
    const int row0 = blockIdx.x * 128;

    {
        const int r = tid >> 1, h = tid & 1;
        const int gr = row0 + r;
#pragma unroll
        for (int i = 0; i < 16; ++i)
            cp16z(sStage + r * 512 + h * 256 + i * 16,
                  B1 + (size_t)gr * 128 + h * 64 + i * 4, gr < n_rows ? 16 : 0);
    }
    const int br = tid >> 4, bq = tid & 15;
    auto loadB = [&](const bf16* Bh, const bf16* Bl) {
#pragma unroll
        for (int seg = 0; seg < 2; ++seg) {
            const bf16* g = seg ? Bl : Bh;
#pragma unroll
            for (int c = 0; c < 4; ++c) {
                cp16z(sB0 + seg * B_SEG + c * B_CHUNK + br * B_STRIDE + bq * 16,
                      g + (size_t)(c * 32 + br) * 128 + bq * 8, 16);
                cp16z(sB0 + seg * B_SEG + c * B_CHUNK + (br + 16) * B_STRIDE + bq * 16,
                      g + (size_t)(c * 32 + br + 16) * 128 + bq * 8, 16);
            }
        }
    };
    loadB(M1hi, M1lo);
    cp_commit();
    cp_wait<0>();
    __syncthreads();

    {
        const int r = tid >> 1, h = tid & 1;
        const int gr = row0 + r;
        const bool ok = gr < n_rows;
#pragma unroll
        for (int j = 0; j < 32; ++j) {
            int col = h * 64 + j * 2;
            float2 v = *(const float2*)(sm + r * 512 + col * 4);
            if (ok) {
                float2 a = *(const float2*)(AGG + (size_t)gr * 128 + col);
                v.x += a.x; v.y += a.y;
            }
            bf16 h0 = __float2bfloat16(v.x), h1 = __float2bfloat16(v.y);
            uint32_t o = (col >> 5) * A_CHUNK + r * A_STRIDE + (col & 31) * 2;
            *(__nv_bfloat162*)(sm + 65536 + o) = __nv_bfloat162(h0, h1);
            *(__nv_bfloat162*)(sm + 65536 + A_SEG + o) = __nv_bfloat162(
                __float2bfloat16(v.x - __bfloat162float(h0)),
                __float2bfloat16(v.y - __bfloat162float(h1)));
        }
    }
    __syncthreads();

    float acc[4][4][4];
#pragma unroll
    for (int f = 0; f < 4; ++f)
#pragma unroll
        for (int g = 0; g < 4; ++g)
#pragma unroll
            for (int r = 0; r < 4; ++r) acc[f][g][r] = 0.f;

    const int arow = lane & 15, ahalf = lane >> 4;
    const int blrow = lane & 15, bnc = (lane >> 4) * 8;
    const int tr = lane >> 2, tc = (lane & 3) * 2;

    auto mma_pass = [&]() {
#pragma unroll
        for (int c = 0; c < 4; ++c) {
#pragma unroll
            for (int s = 0; s < 2; ++s) {
                uint32_t ah[4][4], al[4][4], bh[2][4], bl[2][4];
#pragma unroll
                for (int f = 0; f < 4; ++f) {
                    uint32_t aa = sA0 + c * A_CHUNK + (wm * 64 + f * 16 + arow) * A_STRIDE
                                + (s * 2 + ahalf) * 16;
                    ldsm4(aa,         ah[f][0], ah[f][1], ah[f][2], ah[f][3]);
                    ldsm4(aa + A_SEG, al[f][0], al[f][1], al[f][2], al[f][3]);
                }
#pragma unroll
                for (int g = 0; g < 2; ++g) {
                    uint32_t ba = sB0 + c * B_CHUNK + (s * 16 + blrow) * B_STRIDE
                                + (wn * 32 + g * 16 + bnc) * 2;
                    ldsm4t(ba,         bh[g][0], bh[g][1], bh[g][2], bh[g][3]);
                    ldsm4t(ba + B_SEG, bl[g][0], bl[g][1], bl[g][2], bl[g][3]);
                }
#pragma unroll
                for (int f = 0; f < 4; ++f) {
#pragma unroll
                    for (int g = 0; g < 2; ++g) {
                        mma16816(acc[f][g*2+0][0], acc[f][g*2+0][1], acc[f][g*2+0][2], acc[f][g*2+0][3],
                                 ah[f][0], ah[f][1], ah[f][2], ah[f][3], bh[g][0], bh[g][1]);
                        mma16816(acc[f][g*2+1][0], acc[f][g*2+1][1], acc[f][g*2+1][2], acc[f][g*2+1][3],
                                 ah[f][0], ah[f][1], ah[f][2], ah[f][3], bh[g][2], bh[g][3]);
                        mma16816(acc[f][g*2+0][0], acc[f][g*2+0][1], acc[f][g*2+0][2], acc[f][g*2+0][3],
                                 ah[f][0], ah[f][1], ah[f][2], ah[f][3], bl[g][0], bl[g][1]);
                        mma16816(acc[f][g*2+1][0], acc[f][g*2+1][1], acc[f][g*2+1][2], acc[f][g*2+1][3],
                                 ah[f][0], ah[f][1], ah[f][2], ah[f][3], bl[g][2], bl[g][3]);
                        mma16816(acc[f][g*2+0][0], acc[f][g*2+0][1], acc[f][g*2+0][2], acc[f][g*2+0][3],
                                 al[f][0], al[f][1], al[f][2], al[f][3], bh[g][0], bh[g][1]);
                        mma16816(acc[f][g*2+1][0], acc[f][g*2+1][1], acc[f][g*2+1][2], acc[f][g*2+1][3],
                                 al[f][0], al[f][1], al[f][2], al[f][3], bh[g][2], bh[g][3]);
                    }
                }
            }
        }
    };

    mma_pass();
    __syncthreads();

    loadB(M2hi, M2lo);
    cp_commit();

#pragma unroll
    for (int f = 0; f < 4; ++f) {
        int r0l = wm * 64 + f * 16 + tr;
        int r1l = r0l + 8;
#pragma unroll
        for (int g = 0; g < 4; ++g) {
            int col = wn * 32 + g * 8 + tc;
            float bb0 = m1_b[col], bb1 = m1_b[col + 1];
            float v00 = fmaxf(acc[f][g][0] + bb0, 0.f);
            float v01 = fmaxf(acc[f][g][1] + bb1, 0.f);
            float v10 = fmaxf(acc[f][g][2] + bb0, 0.f);
            float v11 = fmaxf(acc[f][g][3] + bb1, 0.f);
            uint32_t off0 = (col >> 5) * A_CHUNK + r0l * A_STRIDE + (col & 31) * 2;
            uint32_t off1 = (col >> 5) * A_CHUNK + r1l * A_STRIDE + (col & 31) * 2;
            bf16 h00 = __float2bfloat16(v00), h01 = __float2bfloat16(v01);
            bf16 h10 = __float2bfloat16(v10), h11 = __float2bfloat16(v11);
            *(__nv_bfloat162*)(sm + 65536 + off0) = __nv_bfloat162(h00, h01);
            *(__nv_bfloat162*)(sm + 65536 + off1) = __nv_bfloat162(h10, h11);
            *(__nv_bfloat162*)(sm + 65536 + A_SEG + off0) = __nv_bfloat162(
                __float2bfloat16(v00 - __bfloat162float(h00)),
                __float2bfloat16(v01 - __bfloat162float(h01)));
            *(__nv_bfloat162*)(sm + 65536 + A_SEG + off1) = __nv_bfloat162(
                __float2bfloat16(v10 - __bfloat162float(h10)),
                __float2bfloat16(v11 - __bfloat162float(h11)));
            acc[f][g][0] = acc[f][g][1] = acc[f][g][2] = acc[f][g][3] = 0.f;
        }
    }
    cp_wait<0>();
    __syncthreads();

    mma_pass();

#pragma unroll
    for (int f = 0; f < 4; ++f) {
        int m0 = row0 + wm * 64 + f * 16 + tr;
        int m1 = m0 + 8;
#pragma unroll
        for (int g = 0; g < 4; ++g) {
            int col = wn * 32 + g * 8 + tc;
            float bb0 = m2_b[col], bb1 = m2_b[col + 1];
            if (m0 < n_rows)
                *(float2*)(out + (size_t)m0 * 128 + col) =
                    make_float2(acc[f][g][0] + bb0, acc[f][g][1] + bb1);
            if (m1 < n_rows)
                *(float2*)(out + (size_t)m1 * 128 + col) =
                    make_float2(acc[f][g][2] + bb0, acc[f][g][3] + bb1);
        }
    }
}

// ---------------- merged weight split ----------------
__global__ __launch_bounds__(256) void wsplit_kernel(
    const float4* __restrict__ Wrel, const float4* __restrict__ w1W,
    const float4* __restrict__ m1W,  const float4* __restrict__ m2W,
    __nv_bfloat162* __restrict__ Wchi, __nv_bfloat162* __restrict__ Wclo,
    __nv_bfloat162* __restrict__ m1hi, __nv_bfloat162* __restrict__ m1lo,
    __nv_bfloat162* __restrict__ m2hi, __nv_bfloat162* __restrict__ m2lo)
{
    int i = blockIdx.x * 256 + threadIdx.x;
    if (i >= 11 * 4096) return;
    const int mat = i >> 12, local = i & 4095;
    const float4* in;
    __nv_bfloat162 *hi, *lo;
    if (mat < 8)       { in = Wrel + i;    hi = Wchi + i * 2;                  lo = Wclo + i * 2; }
    else if (mat == 8) { in = w1W + local; hi = Wchi + (8 * 4096 + local) * 2; lo = Wclo + (8 * 4096 + local) * 2; }
    else if (mat == 9) { in = m1W + local; hi = m1hi + local * 2;              lo = m1lo + local * 2; }
    else               { in = m2W + local; hi = m2hi + local * 2;              lo = m2lo + local * 2; }
    float4 v = *in;
    bf16 hx = __float2bfloat16(v.x), hy = __float2bfloat16(v.y);
    bf16 hz = __float2bfloat16(v.z), hw = __float2bfloat16(v.w);
    hi[0] = __nv_bfloat162(hx, hy);
    hi[1] = __nv_bfloat162(hz, hw);
    lo[0] = __nv_bfloat162(__float2bfloat16(v.x - __bfloat162float(hx)),
                           __float2bfloat16(v.y - __bfloat162float(hy)));
    lo[1] = __nv_bfloat162(__float2bfloat16(v.z - __bfloat162float(hz)),
                           __float2bfloat16(v.w - __bfloat162float(hw)));
}

// ---------------- launch ----------------
extern "C" void kernel_launch(void* const* d_in, const int* in_sizes, int n_in,
                              void* d_out, int out_size)
{
    const float* x     = (const float*)d_in[0];
    const int*   src   = (const int*)  d_in[1];
    const int*   dst   = (const int*)  d_in[2];
    const int*   etype = (const int*)  d_in[3];
    const float* W_rel = (const float*)d_in[4];
    const float* w1_W  = (const float*)d_in[5];
    const float* w1_b  = (const float*)d_in[6];
    const float* m1_W  = (const float*)d_in[7];
    const float* m1_b  = (const float*)d_in[8];
    const float* m2_W  = (const float*)d_in[9];
    const float* m2_b  = (const float*)d_in[10];
    float* out = (float*)d_out;

    float *b1, *agg;
    bf16 *Wchi, *Wclo, *m1hi, *m1lo, *m2hi, *m2lo;
    uint32_t* epack;
    int *hist, *off, *cur;
    cudaGetSymbolAddress((void**)&b1,    g_b1);
    cudaGetSymbolAddress((void**)&agg,   g_agg);
    cudaGetSymbolAddress((void**)&Wchi,  g_Wchi);
    cudaGetSymbolAddress((void**)&Wclo,  g_Wclo);
    cudaGetSymbolAddress((void**)&m1hi,  g_m1hi);
    cudaGetSymbolAddress((void**)&m1lo,  g_m1lo);
    cudaGetSymbolAddress((void**)&m2hi,  g_m2hi);
    cudaGetSymbolAddress((void**)&m2lo,  g_m2lo);
    cudaGetSymbolAddress((void**)&epack, g_epack);
    cudaGetSymbolAddress((void**)&hist,  g_hist);
    cudaGetSymbolAddress((void**)&off,   g_off);
    cudaGetSymbolAddress((void**)&cur,   g_cur);

    cudaFuncSetAttribute(rgemm_fused, cudaFuncAttributeMaxDynamicSharedMemorySize, FUSED_SMEM);
    cudaFuncSetAttribute(mlp_fused,   cudaFuncAttributeMaxDynamicSharedMemorySize, MLP_SMEM);

    // prep: zero hist + agg; split weights; bucket edges
    cudaMemsetAsync(hist, 0, NB * sizeof(int));
    cudaMemsetAsync(agg, 0, (size_t)Nn * 128 * sizeof(float));
    wsplit_kernel<<<(11 * 4096 + 255) / 256, 256>>>(
        (const float4*)W_rel, (const float4*)w1_W,
        (const float4*)m1_W, (const float4*)m2_W,
        (__nv_bfloat162*)Wchi, (__nv_bfloat162*)Wclo,
        (__nv_bfloat162*)m1hi, (__nv_bfloat162*)m1lo,
        (__nv_bfloat162*)m2hi, (__nv_bfloat162*)m2lo);
    hist_kernel<<<(Ee + 255) / 256, 256>>>(src, etype, hist);
    scan_kernel<<<1, 1024>>>(hist, off, cur);
    esort_kernel<<<(Ee + 255) / 256, 256>>>(src, dst, etype, cur, epack);

    // relation GEMMs + w1 GEMM + in-place edge scatter into agg
    rgemm_fused<<<NT, 256, FUSED_SMEM>>>(x, Wchi, Wclo, w1_b, epack, off, agg, b1, Nn);

    // out = relu((b1+agg)@m1 + b)@m2 + b
    mlp_fused<<<NT, 256, MLP_SMEM>>>(b1, agg, m1hi, m1lo, m2hi, m2lo,
                                     m1_b, m2_b, out, Nn);
}

// round 9
// speedup vs baseline: 1.1250x; 1.1250x over previous
#include <cuda_runtime.h>
#include <cuda_bf16.h>
#include <cstdint>

#define Nn 50000
#define Ee 640000
#define Rr 8
typedef __nv_bfloat16 bf16;

// ---------------- scratch ----------------
__device__ float g_hall[(size_t)Rr * Nn * 128];
__device__ float g_b1[(size_t)Nn * 128];
__device__ bf16  g_Wchi[9 * 128 * 128], g_Wclo[9 * 128 * 128];   // 8 rels + w1
__device__ bf16  g_m1hi[128 * 128], g_m1lo[128 * 128];
__device__ bf16  g_m2hi[128 * 128], g_m2lo[128 * 128];

// ---------------- asm helpers ----------------
__device__ __forceinline__ uint32_t s2u(const void* p) {
    return (uint32_t)__cvta_generic_to_shared(p);
}
__device__ __forceinline__ void cp16z(uint32_t d, const void* s, int sz) {
    asm volatile("cp.async.cg.shared.global [%0],[%1],16,%2;\n" :: "r"(d), "l"(s), "r"(sz));
}
__device__ __forceinline__ void cp_commit() { asm volatile("cp.async.commit_group;\n"); }
template<int N> __device__ __forceinline__ void cp_wait() {
    asm volatile("cp.async.wait_group %0;\n" :: "n"(N));
}
__device__ __forceinline__ void ldsm4(uint32_t a, uint32_t& r0, uint32_t& r1,
                                      uint32_t& r2, uint32_t& r3) {
    asm volatile("ldmatrix.sync.aligned.m8n8.x4.shared.b16 {%0,%1,%2,%3}, [%4];"
                 : "=r"(r0), "=r"(r1), "=r"(r2), "=r"(r3) : "r"(a));
}
__device__ __forceinline__ void ldsm4t(uint32_t a, uint32_t& r0, uint32_t& r1,
                                       uint32_t& r2, uint32_t& r3) {
    asm volatile("ldmatrix.sync.aligned.m8n8.x4.trans.shared.b16 {%0,%1,%2,%3}, [%4];"
                 : "=r"(r0), "=r"(r1), "=r"(r2), "=r"(r3) : "r"(a));
}
__device__ __forceinline__ void mma16816(float& d0, float& d1, float& d2, float& d3,
                                         uint32_t a0, uint32_t a1, uint32_t a2, uint32_t a3,
                                         uint32_t b0, uint32_t b1) {
    asm volatile(
        "mma.sync.aligned.m16n8k16.row.col.f32.bf16.bf16.f32 "
        "{%0,%1,%2,%3}, {%4,%5,%6,%7}, {%8,%9}, {%0,%1,%2,%3};"
        : "+f"(d0), "+f"(d1), "+f"(d2), "+f"(d3)
        : "r"(a0), "r"(a1), "r"(a2), "r"(a3), "r"(b0), "r"(b1));
}

#define A_STRIDE 80
#define A_CHUNK  (128 * A_STRIDE)   // 10240
#define A_SEG    (4 * A_CHUNK)      // 40960
#define B_STRIDE 272
#define B_CHUNK  (32 * B_STRIDE)    // 8704
#define B_SEG    (4 * B_CHUNK)      // 34816
#define B_BUF    (2 * B_SEG)        // 69632
#define FUSED_SMEM (2 * A_SEG + 2 * B_BUF)            // 221184
#define MLP_SMEM   (65536 + 2 * A_SEG + 2 * B_SEG)    // 217088

// ================= fused relation GEMM, parameterized rel range =================
// Computes hall[r] = x @ W[r] for r in [rel0, rel0+nrels), plus (if doW1)
// b1 = x @ w1 + w1_b.  fp32 x staged + split in-kernel.
__global__ __launch_bounds__(256, 1) void rgemm_fused(
    const float* __restrict__ X,
    const bf16* __restrict__ Whi, const bf16* __restrict__ Wlo,
    const float* __restrict__ w1_b,
    float* __restrict__ hall, float* __restrict__ b1, int n_rows,
    int rel0, int nrels, int doW1)
{
    extern __shared__ __align__(16) char sm[];
    const uint32_t sA0 = s2u(sm);
    const uint32_t sB0 = sA0 + 2 * A_SEG;

    const int tid = threadIdx.x, lane = tid & 31, wid = tid >> 5;
    const int wm = wid & 1, wn = wid >> 1;
    const int row0 = blockIdx.x * 128;
    const int total = nrels + doW1;

    // ---- stage fp32 x tile into sB area, split to sA hi/lo ----
    {
        const int r = tid >> 1, h = tid & 1;
        const int gr = row0 + r;
#pragma unroll
        for (int i = 0; i < 16; ++i)
            cp16z(sB0 + r * 512 + h * 256 + i * 16,
                  X + (size_t)gr * 128 + h * 64 + i * 4, gr < n_rows ? 16 : 0);
        cp_commit();
        cp_wait<0>();
        __syncthreads();
#pragma unroll
        for (int j = 0; j < 32; ++j) {
            int col = h * 64 + j * 2;
            float2 v = *(const float2*)(sm + 2 * A_SEG + r * 512 + col * 4);
            bf16 h0 = __float2bfloat16(v.x), h1 = __float2bfloat16(v.y);
            uint32_t o = (col >> 5) * A_CHUNK + r * A_STRIDE + (col & 31) * 2;
            *(__nv_bfloat162*)(sm + o) = __nv_bfloat162(h0, h1);
            *(__nv_bfloat162*)(sm + A_SEG + o) = __nv_bfloat162(
                __float2bfloat16(v.x - __bfloat162float(h0)),
                __float2bfloat16(v.y - __bfloat162float(h1)));
        }
        __syncthreads();
    }

    const int br = tid >> 4, bq = tid & 15;
    auto matOf = [&](int i) { return (i < nrels) ? (rel0 + i) : 8; };
    auto loadB = [&](int mat, int buf) {
#pragma unroll
        for (int seg = 0; seg < 2; ++seg) {
            const bf16* g = (seg ? Wlo : Whi) + (size_t)mat * 16384;
#pragma unroll
            for (int c = 0; c < 4; ++c) {
                cp16z(sB0 + buf * B_BUF + seg * B_SEG + c * B_CHUNK + br * B_STRIDE + bq * 16,
                      g + (size_t)(c * 32 + br) * 128 + bq * 8, 16);
                cp16z(sB0 + buf * B_BUF + seg * B_SEG + c * B_CHUNK + (br + 16) * B_STRIDE + bq * 16,
                      g + (size_t)(c * 32 + br + 16) * 128 + bq * 8, 16);
            }
        }
    };
    loadB(matOf(0), 0);
    cp_commit();

    float acc[4][4][4];
#pragma unroll
    for (int f = 0; f < 4; ++f)
#pragma unroll
        for (int g = 0; g < 4; ++g)
#pragma unroll
            for (int r = 0; r < 4; ++r) acc[f][g][r] = 0.f;

    const int arow = lane & 15, ahalf = lane >> 4;
    const int blrow = lane & 15, bnc = (lane >> 4) * 8;
    const int tr = lane >> 2, tc = (lane & 3) * 2;

    for (int i = 0; i < total; ++i) {
        const int buf = i & 1;
        cp_wait<0>();
        __syncthreads();
        if (i + 1 < total) { loadB(matOf(i + 1), buf ^ 1); cp_commit(); }

        const uint32_t bB = sB0 + buf * B_BUF;
#pragma unroll
        for (int c = 0; c < 4; ++c) {
#pragma unroll
            for (int s = 0; s < 2; ++s) {
                uint32_t ah[4][4], al[4][4], bh[2][4], bl[2][4];
#pragma unroll
                for (int f = 0; f < 4; ++f) {
                    uint32_t aa = sA0 + c * A_CHUNK + (wm * 64 + f * 16 + arow) * A_STRIDE
                                + (s * 2 + ahalf) * 16;
                    ldsm4(aa,         ah[f][0], ah[f][1], ah[f][2], ah[f][3]);
                    ldsm4(aa + A_SEG, al[f][0], al[f][1], al[f][2], al[f][3]);
                }
#pragma unroll
                for (int g = 0; g < 2; ++g) {
                    uint32_t ba = bB + c * B_CHUNK + (s * 16 + blrow) * B_STRIDE
                                + (wn * 32 + g * 16 + bnc) * 2;
                    ldsm4t(ba,         bh[g][0], bh[g][1], bh[g][2], bh[g][3]);
                    ldsm4t(ba + B_SEG, bl[g][0], bl[g][1], bl[g][2], bl[g][3]);
                }
#pragma unroll
                for (int f = 0; f < 4; ++f) {
#pragma unroll
                    for (int g = 0; g < 2; ++g) {
                        mma16816(acc[f][g*2+0][0], acc[f][g*2+0][1], acc[f][g*2+0][2], acc[f][g*2+0][3],
                                 ah[f][0], ah[f][1], ah[f][2], ah[f][3], bh[g][0], bh[g][1]);
                        mma16816(acc[f][g*2+1][0], acc[f][g*2+1][1], acc[f][g*2+1][2], acc[f][g*2+1][3],
                                 ah[f][0], ah[f][1], ah[f][2], ah[f][3], bh[g][2], bh[g][3]);
                        mma16816(acc[f][g*2+0][0], acc[f][g*2+0][1], acc[f][g*2+0][2], acc[f][g*2+0][3],
                                 ah[f][0], ah[f][1], ah[f][2], ah[f][3], bl[g][0], bl[g][1]);
                        mma16816(acc[f][g*2+1][0], acc[f][g*2+1][1], acc[f][g*2+1][2], acc[f][g*2+1][3],
                                 ah[f][0], ah[f][1], ah[f][2], ah[f][3], bl[g][2], bl[g][3]);
                        mma16816(acc[f][g*2+0][0], acc[f][g*2+0][1], acc[f][g*2+0][2], acc[f][g*2+0][3],
                                 al[f][0], al[f][1], al[f][2], al[f][3], bh[g][0], bh[g][1]);
                        mma16816(acc[f][g*2+1][0], acc[f][g*2+1][1], acc[f][g*2+1][2], acc[f][g*2+1][3],
                                 al[f][0], al[f][1], al[f][2], al[f][3], bh[g][2], bh[g][3]);
                    }
                }
            }
        }

        const int mat = matOf(i);
        float* C = (mat < 8) ? (hall + (size_t)mat * Nn * 128) : b1;
        const bool useBias = (mat == 8);
#pragma unroll
        for (int f = 0; f < 4; ++f) {
            int m0 = row0 + wm * 64 + f * 16 + tr;
            int m1 = m0 + 8;
#pragma unroll
            for (int g = 0; g < 4; ++g) {
                int col = wn * 32 + g * 8 + tc;
                float v00 = acc[f][g][0], v01 = acc[f][g][1];
                float v10 = acc[f][g][2], v11 = acc[f][g][3];
                if (useBias) {
                    float bb0 = w1_b[col], bb1 = w1_b[col + 1];
                    v00 += bb0; v01 += bb1; v10 += bb0; v11 += bb1;
                }
                if (m0 < n_rows) *(float2*)(C + (size_t)m0 * 128 + col) = make_float2(v00, v01);
                if (m1 < n_rows) *(float2*)(C + (size_t)m1 * 128 + col) = make_float2(v10, v11);
                acc[f][g][0] = acc[f][g][1] = acc[f][g][2] = acc[f][g][3] = 0.f;
            }
        }
    }
}

// ================= fused MLP (proven round 7) =================
__global__ __launch_bounds__(256, 1) void mlp_fused(
    const float* __restrict__ B1,
    const bf16* __restrict__ M1hi, const bf16* __restrict__ M1lo,
    const bf16* __restrict__ M2hi, const bf16* __restrict__ M2lo,
    const float* __restrict__ m1_b, const float* __restrict__ m2_b,
    float* __restrict__ out, int n_rows)
{
    extern __shared__ __align__(16) char sm[];
    const uint32_t sStage = s2u(sm);
    const uint32_t sA0 = sStage + 65536;
    const uint32_t sB0 = sA0 + 2 * A_SEG;

    const int tid = threadIdx.x, lane = tid & 31, wid = tid >> 5;
    const int wm = wid & 1, wn = wid >> 1;
    const int row0 = blockIdx.x * 128;

    {
        const int r = tid >> 1, h = tid & 1;
        const int gr = row0 + r;
#pragma unroll
        for (int i = 0; i < 16; ++i)
            cp16z(sStage + r * 512 + h * 256 + i * 16,
                  B1 + (size_t)gr * 128 + h * 64 + i * 4, gr < n_rows ? 16 : 0);
    }
    const int br = tid >> 4, bq = tid & 15;
    auto loadB = [&](const bf16* Bh, const bf16* Bl) {
#pragma unroll
        for (int seg = 0; seg < 2; ++seg) {
            const bf16* g = seg ? Bl : Bh;
#pragma unroll
            for (int c = 0; c < 4; ++c) {
                cp16z(sB0 + seg * B_SEG + c * B_CHUNK + br * B_STRIDE + bq * 16,
                      g + (size_t)(c * 32 + br) * 128 + bq * 8, 16);
                cp16z(sB0 + seg * B_SEG + c * B_CHUNK + (br + 16) * B_STRIDE + bq * 16,
                      g + (size_t)(c * 32 + br + 16) * 128 + bq * 8, 16);
            }
        }
    };
    loadB(M1hi, M1lo);
    cp_commit();
    cp_wait<0>();
    __syncthreads();

    {
        const int r = tid >> 1, h = tid & 1;
#pragma unroll
        for (int j = 0; j < 32; ++j) {
            int col = h * 64 + j * 2;
            float2 v = *(const float2*)(sm + r * 512 + col * 4);
            bf16 h0 = __float2bfloat16(v.x), h1 = __float2bfloat16(v.y);
            uint32_t o = (col >> 5) * A_CHUNK + r * A_STRIDE + (col & 31) * 2;
            *(__nv_bfloat162*)(sm + 65536 + o) = __nv_bfloat162(h0, h1);
            *(__nv_bfloat162*)(sm + 65536 + A_SEG + o) = __nv_bfloat162(
                __float2bfloat16(v.x - __bfloat162float(h0)),
                __float2bfloat16(v.y - __bfloat162float(h1)));
        }
    }
    __syncthreads();

    float acc[4][4][4];
#pragma unroll
    for (int f = 0; f < 4; ++f)
#pragma unroll
        for (int g = 0; g < 4; ++g)
#pragma unroll
            for (int r = 0; r < 4; ++r) acc[f][g][r] = 0.f;

    const int arow = lane & 15, ahalf = lane >> 4;
    const int blrow = lane & 15, bnc = (lane >> 4) * 8;
    const int tr = lane >> 2, tc = (lane & 3) * 2;

    auto mma_pass = [&]() {
#pragma unroll
        for (int c = 0; c < 4; ++c) {
#pragma unroll
            for (int s = 0; s < 2; ++s) {
                uint32_t ah[4][4], al[4][4], bh[2][4], bl[2][4];
#pragma unroll
                for (int f = 0; f < 4; ++f) {
                    uint32_t aa = sA0 + c * A_CHUNK + (wm * 64 + f * 16 + arow) * A_STRIDE
                                + (s * 2 + ahalf) * 16;
                    ldsm4(aa,         ah[f][0], ah[f][1], ah[f][2], ah[f][3]);
                    ldsm4(aa + A_SEG, al[f][0], al[f][1], al[f][2], al[f][3]);
                }
#pragma unroll
                for (int g = 0; g < 2; ++g) {
                    uint32_t ba = sB0 + c * B_CHUNK + (s * 16 + blrow) * B_STRIDE
                                + (wn * 32 + g * 16 + bnc) * 2;
                    ldsm4t(ba,         bh[g][0], bh[g][1], bh[g][2], bh[g][3]);
                    ldsm4t(ba + B_SEG, bl[g][0], bl[g][1], bl[g][2], bl[g][3]);
                }
#pragma unroll
                for (int f = 0; f < 4; ++f) {
#pragma unroll
                    for (int g = 0; g < 2; ++g) {
                        mma16816(acc[f][g*2+0][0], acc[f][g*2+0][1], acc[f][g*2+0][2], acc[f][g*2+0][3],
                                 ah[f][0], ah[f][1], ah[f][2], ah[f][3], bh[g][0], bh[g][1]);
                        mma16816(acc[f][g*2+1][0], acc[f][g*2+1][1], acc[f][g*2+1][2], acc[f][g*2+1][3],
                                 ah[f][0], ah[f][1], ah[f][2], ah[f][3], bh[g][2], bh[g][3]);
                        mma16816(acc[f][g*2+0][0], acc[f][g*2+0][1], acc[f][g*2+0][2], acc[f][g*2+0][3],
                                 ah[f][0], ah[f][1], ah[f][2], ah[f][3], bl[g][0], bl[g][1]);
                        mma16816(acc[f][g*2+1][0], acc[f][g*2+1][1], acc[f][g*2+1][2], acc[f][g*2+1][3],
                                 ah[f][0], ah[f][1], ah[f][2], ah[f][3], bl[g][2], bl[g][3]);
                        mma16816(acc[f][g*2+0][0], acc[f][g*2+0][1], acc[f][g*2+0][2], acc[f][g*2+0][3],
                                 al[f][0], al[f][1], al[f][2], al[f][3], bh[g][0], bh[g][1]);
                        mma16816(acc[f][g*2+1][0], acc[f][g*2+1][1], acc[f][g*2+1][2], acc[f][g*2+1][3],
                                 al[f][0], al[f][1], al[f][2], al[f][3], bh[g][2], bh[g][3]);
                    }
                }
            }
        }
    };

    mma_pass();
    __syncthreads();

    loadB(M2hi, M2lo);
    cp_commit();

#pragma unroll
    for (int f = 0; f < 4; ++f) {
        int r0l = wm * 64 + f * 16 + tr;
        int r1l = r0l + 8;
#pragma unroll
        for (int g = 0; g < 4; ++g) {
            int col = wn * 32 + g * 8 + tc;
            float bb0 = m1_b[col], bb1 = m1_b[col + 1];
            float v00 = fmaxf(acc[f][g][0] + bb0, 0.f);
            float v01 = fmaxf(acc[f][g][1] + bb1, 0.f);
            float v10 = fmaxf(acc[f][g][2] + bb0, 0.f);
            float v11 = fmaxf(acc[f][g][3] + bb1, 0.f);
            uint32_t off0 = (col >> 5) * A_CHUNK + r0l * A_STRIDE + (col & 31) * 2;
            uint32_t off1 = (col >> 5) * A_CHUNK + r1l * A_STRIDE + (col & 31) * 2;
            bf16 h00 = __float2bfloat16(v00), h01 = __float2bfloat16(v01);
            bf16 h10 = __float2bfloat16(v10), h11 = __float2bfloat16(v11);
            *(__nv_bfloat162*)(sm + 65536 + off0) = __nv_bfloat162(h00, h01);
            *(__nv_bfloat162*)(sm + 65536 + off1) = __nv_bfloat162(h10, h11);
            *(__nv_bfloat162*)(sm + 65536 + A_SEG + off0) = __nv_bfloat162(
                __float2bfloat16(v00 - __bfloat162float(h00)),
                __float2bfloat16(v01 - __bfloat162float(h01)));
            *(__nv_bfloat162*)(sm + 65536 + A_SEG + off1) = __nv_bfloat162(
                __float2bfloat16(v10 - __bfloat162float(h10)),
                __float2bfloat16(v11 - __bfloat162float(h11)));
            acc[f][g][0] = acc[f][g][1] = acc[f][g][2] = acc[f][g][3] = 0.f;
        }
    }
    cp_wait<0>();
    __syncthreads();

    mma_pass();

#pragma unroll
    for (int f = 0; f < 4; ++f) {
        int m0 = row0 + wm * 64 + f * 16 + tr;
        int m1 = m0 + 8;
#pragma unroll
        for (int g = 0; g < 4; ++g) {
            int col = wn * 32 + g * 8 + tc;
            float bb0 = m2_b[col], bb1 = m2_b[col + 1];
            if (m0 < n_rows)
                *(float2*)(out + (size_t)m0 * 128 + col) =
                    make_float2(acc[f][g][0] + bb0, acc[f][g][1] + bb1);
            if (m1 < n_rows)
                *(float2*)(out + (size_t)m1 * 128 + col) =
                    make_float2(acc[f][g][2] + bb0, acc[f][g][3] + bb1);
        }
    }
}

// ---------------- merged weight split ----------------
__global__ __launch_bounds__(256) void wsplit_kernel(
    const float4* __restrict__ Wrel, const float4* __restrict__ w1W,
    const float4* __restrict__ m1W,  const float4* __restrict__ m2W,
    __nv_bfloat162* __restrict__ Wchi, __nv_bfloat162* __restrict__ Wclo,
    __nv_bfloat162* __restrict__ m1hi, __nv_bfloat162* __restrict__ m1lo,
    __nv_bfloat162* __restrict__ m2hi, __nv_bfloat162* __restrict__ m2lo)
{
    int i = blockIdx.x * 256 + threadIdx.x;
    if (i >= 11 * 4096) return;
    const int mat = i >> 12, local = i & 4095;
    const float4* in;
    __nv_bfloat162 *hi, *lo;
    if (mat < 8)       { in = Wrel + i;    hi = Wchi + i * 2;                  lo = Wclo + i * 2; }
    else if (mat == 8) { in = w1W + local; hi = Wchi + (8 * 4096 + local) * 2; lo = Wclo + (8 * 4096 + local) * 2; }
    else if (mat == 9) { in = m1W + local; hi = m1hi + local * 2;              lo = m1lo + local * 2; }
    else               { in = m2W + local; hi = m2hi + local * 2;              lo = m2lo + local * 2; }
    float4 v = *in;
    bf16 hx = __float2bfloat16(v.x), hy = __float2bfloat16(v.y);
    bf16 hz = __float2bfloat16(v.z), hw = __float2bfloat16(v.w);
    hi[0] = __nv_bfloat162(hx, hy);
    hi[1] = __nv_bfloat162(hz, hw);
    lo[0] = __nv_bfloat162(__float2bfloat16(v.x - __bfloat162float(hx)),
                           __float2bfloat16(v.y - __bfloat162float(hy)));
    lo[1] = __nv_bfloat162(__float2bfloat16(v.z - __bfloat162float(hz)),
                           __float2bfloat16(v.w - __bfloat162float(hw)));
}

// ---------------- edge scatter: 8 edges per warp, etype-filtered ----------------
__global__ __launch_bounds__(256) void edge_scatter(
    const float* __restrict__ hall,
    const int* __restrict__ src, const int* __restrict__ dst,
    const int* __restrict__ etype, float* __restrict__ agg,
    int t0, int t1)
{
    const int w    = (blockIdx.x * 256 + threadIdx.x) >> 5;
    const int lane = threadIdx.x & 31;
    const int e0   = w * 8;
    if (e0 >= Ee) return;

    int s[8], d[8], t[8];
    bool ok[8];
#pragma unroll
    for (int i = 0; i < 8; ++i) {
        s[i] = __ldg(src + e0 + i);
        d[i] = __ldg(dst + e0 + i);
        t[i] = __ldg(etype + e0 + i);
        ok[i] = (t[i] >= t0) & (t[i] < t1);
    }
    float4 v[8];
#pragma unroll
    for (int i = 0; i < 8; ++i)
        if (ok[i])
            v[i] = ((const float4*)(hall + ((size_t)t[i] * Nn + s[i]) * 128))[lane];
#pragma unroll
    for (int i = 0; i < 8; ++i) {
        if (!ok[i]) continue;
        float* o = agg + (size_t)d[i] * 128 + lane * 4;
        asm volatile("red.global.add.v4.f32 [%0], {%1,%2,%3,%4};"
                     :: "l"(o), "f"(v[i].x), "f"(v[i].y), "f"(v[i].z), "f"(v[i].w) : "memory");
    }
}

// ---------------- launch ----------------
extern "C" void kernel_launch(void* const* d_in, const int* in_sizes, int n_in,
                              void* d_out, int out_size)
{
    const float* x     = (const float*)d_in[0];
    const int*   src   = (const int*)  d_in[1];
    const int*   dst   = (const int*)  d_in[2];
    const int*   etype = (const int*)  d_in[3];
    const float* W_rel = (const float*)d_in[4];
    const float* w1_W  = (const float*)d_in[5];
    const float* w1_b  = (const float*)d_in[6];
    const float* m1_W  = (const float*)d_in[7];
    const float* m1_b  = (const float*)d_in[8];
    const float* m2_W  = (const float*)d_in[9];
    const float* m2_b  = (const float*)d_in[10];
    float* out = (float*)d_out;

    float *hall, *b1;
    bf16 *Wchi, *Wclo, *m1hi, *m1lo, *m2hi, *m2lo;
    cudaGetSymbolAddress((void**)&hall, g_hall);
    cudaGetSymbolAddress((void**)&b1,   g_b1);
    cudaGetSymbolAddress((void**)&Wchi, g_Wchi);
    cudaGetSymbolAddress((void**)&Wclo, g_Wclo);
    cudaGetSymbolAddress((void**)&m1hi, g_m1hi);
    cudaGetSymbolAddress((void**)&m1lo, g_m1lo);
    cudaGetSymbolAddress((void**)&m2hi, g_m2hi);
    cudaGetSymbolAddress((void**)&m2lo, g_m2lo);

    cudaFuncSetAttribute(rgemm_fused, cudaFuncAttributeMaxDynamicSharedMemorySize, FUSED_SMEM);
    cudaFuncSetAttribute(mlp_fused,   cudaFuncAttributeMaxDynamicSharedMemorySize, MLP_SMEM);

    const int nTiles = (Nn + 127) / 128;  // 391
    const int sgrid  = (Ee / 8 + 7) / 8;  // 8 edges/warp, 8 warps/block -> 10000

    cudaStream_t s2;
    cudaStreamCreate(&s2);
    cudaEvent_t evA, evB, evJ;
    cudaEventCreateWithFlags(&evA, cudaEventDisableTiming);
    cudaEventCreateWithFlags(&evB, cudaEventDisableTiming);
    cudaEventCreateWithFlags(&evJ, cudaEventDisableTiming);

    // default stream: weight split, then rgemm in two chunks
    wsplit_kernel<<<(11 * 4096 + 255) / 256, 256>>>(
        (const float4*)W_rel, (const float4*)w1_W,
        (const float4*)m1_W, (const float4*)m2_W,
        (__nv_bfloat162*)Wchi, (__nv_bfloat162*)Wclo,
        (__nv_bfloat162*)m1hi, (__nv_bfloat162*)m1lo,
        (__nv_bfloat162*)m2hi, (__nv_bfloat162*)m2lo);

    // chunk A: rels 0-5 + w1 (b1 ready after this)
    rgemm_fused<<<nTiles, 256, FUSED_SMEM>>>(
        x, Wchi, Wclo, w1_b, hall, b1, Nn, 0, 6, 1);
    cudaEventRecord(evA, 0);

    // chunk B: rels 6-7 (overlaps scatterA on s2)
    rgemm_fused<<<nTiles, 256, FUSED_SMEM>>>(
        x, Wchi, Wclo, w1_b, hall, b1, Nn, 6, 2, 0);
    cudaEventRecord(evB, 0);

    // s2: scatter etype 0-5 after chunk A; etype 6-7 after chunk B
    cudaStreamWaitEvent(s2, evA, 0);
    edge_scatter<<<sgrid, 256, 0, s2>>>(hall, src, dst, etype, b1, 0, 6);
    cudaStreamWaitEvent(s2, evB, 0);
    edge_scatter<<<sgrid, 256, 0, s2>>>(hall, src, dst, etype, b1, 6, 8);
    cudaEventRecord(evJ, s2);

    // rejoin and finish on default stream
    cudaStreamWaitEvent(0, evJ, 0);
    mlp_fused<<<nTiles, 256, MLP_SMEM>>>(b1, m1hi, m1lo, m2hi, m2lo,
                                         m1_b, m2_b, out, Nn);

    cudaEventDestroy(evA);
    cudaEventDestroy(evB);
    cudaEventDestroy(evJ);
    cudaStreamDestroy(s2);
}

// round 11
// speedup vs baseline: 1.2879x; 1.1448x over previous
#include <cuda_runtime.h>
#include <cuda_bf16.h>
#include <cstdint>

#define Nn 50000
#define Ee 640000
#define Rr 8
typedef __nv_bfloat16 bf16;

// ---------------- scratch ----------------
__device__ float g_hall[(size_t)Rr * Nn * 128];
__device__ float g_b1[(size_t)Nn * 128];
__device__ bf16  g_Wchi[9 * 128 * 128], g_Wclo[9 * 128 * 128];   // 8 rels + w1
__device__ bf16  g_m1hi[128 * 128], g_m1lo[128 * 128];
__device__ bf16  g_m2hi[128 * 128], g_m2lo[128 * 128];

// ---------------- asm helpers ----------------
__device__ __forceinline__ uint32_t s2u(const void* p) {
    return (uint32_t)__cvta_generic_to_shared(p);
}
__device__ __forceinline__ void cp16z(uint32_t d, const void* s, int sz) {
    asm volatile("cp.async.cg.shared.global [%0],[%1],16,%2;\n" :: "r"(d), "l"(s), "r"(sz));
}
__device__ __forceinline__ void cp_commit() { asm volatile("cp.async.commit_group;\n"); }
template<int N> __device__ __forceinline__ void cp_wait() {
    asm volatile("cp.async.wait_group %0;\n" :: "n"(N));
}
__device__ __forceinline__ void ldsm4(uint32_t a, uint32_t& r0, uint32_t& r1,
                                      uint32_t& r2, uint32_t& r3) {
    asm volatile("ldmatrix.sync.aligned.m8n8.x4.shared.b16 {%0,%1,%2,%3}, [%4];"
                 : "=r"(r0), "=r"(r1), "=r"(r2), "=r"(r3) : "r"(a));
}
__device__ __forceinline__ void ldsm4t(uint32_t a, uint32_t& r0, uint32_t& r1,
                                       uint32_t& r2, uint32_t& r3) {
    asm volatile("ldmatrix.sync.aligned.m8n8.x4.trans.shared.b16 {%0,%1,%2,%3}, [%4];"
                 : "=r"(r0), "=r"(r1), "=r"(r2), "=r"(r3) : "r"(a));
}
__device__ __forceinline__ void mma16816(float& d0, float& d1, float& d2, float& d3,
                                         uint32_t a0, uint32_t a1, uint32_t a2, uint32_t a3,
                                         uint32_t b0, uint32_t b1) {
    asm volatile(
        "mma.sync.aligned.m16n8k16.row.col.f32.bf16.bf16.f32 "
        "{%0,%1,%2,%3}, {%4,%5,%6,%7}, {%8,%9}, {%0,%1,%2,%3};"
        : "+f"(d0), "+f"(d1), "+f"(d2), "+f"(d3)
        : "r"(a0), "r"(a1), "r"(a2), "r"(a3), "r"(b0), "r"(b1));
}

#define A_STRIDE 80
#define A_CHUNK  (128 * A_STRIDE)   // 10240
#define A_SEG    (4 * A_CHUNK)      // 40960
#define B_STRIDE 272
#define B_CHUNK  (32 * B_STRIDE)    // 8704
#define B_SEG    (4 * B_CHUNK)      // 34816
#define B_BUF    (2 * B_SEG)        // 69632
#define FUSED_SMEM (2 * A_SEG + 2 * B_BUF)            // 221184
#define MLP_SMEM   (65536 + 2 * A_SEG + 2 * B_SEG)    // 217088

// ================= fused relation GEMM (round-7 proven; w1 first) =================
// mat order: w1 (i=0), then rels 0..7.  fp32 x staged + split in-kernel.
__global__ __launch_bounds__(256, 1) void rgemm_fused(
    const float* __restrict__ X,
    const bf16* __restrict__ Whi, const bf16* __restrict__ Wlo,
    const float* __restrict__ w1_b,
    float* __restrict__ hall, float* __restrict__ b1, int n_rows)
{
    extern __shared__ __align__(16) char sm[];
    const uint32_t sA0 = s2u(sm);
    const uint32_t sB0 = sA0 + 2 * A_SEG;

    const int tid = threadIdx.x, lane = tid & 31, wid = tid >> 5;
    const int wm = wid & 1, wn = wid >> 1;
    const int row0 = blockIdx.x * 128;

    // ---- stage fp32 x tile into sB area, split to sA hi/lo ----
    {
        const int r = tid >> 1, h = tid & 1;
        const int gr = row0 + r;
#pragma unroll
        for (int i = 0; i < 16; ++i)
            cp16z(sB0 + r * 512 + h * 256 + i * 16,
                  X + (size_t)gr * 128 + h * 64 + i * 4, gr < n_rows ? 16 : 0);
        cp_commit();
        cp_wait<0>();
        __syncthreads();
#pragma unroll
        for (int j = 0; j < 32; ++j) {
            int col = h * 64 + j * 2;
            float2 v = *(const float2*)(sm + 2 * A_SEG + r * 512 + col * 4);
            bf16 h0 = __float2bfloat16(v.x), h1 = __float2bfloat16(v.y);
            uint32_t o = (col >> 5) * A_CHUNK + r * A_STRIDE + (col & 31) * 2;
            *(__nv_bfloat162*)(sm + o) = __nv_bfloat162(h0, h1);
            *(__nv_bfloat162*)(sm + A_SEG + o) = __nv_bfloat162(
                __float2bfloat16(v.x - __bfloat162float(h0)),
                __float2bfloat16(v.y - __bfloat162float(h1)));
        }
        __syncthreads();
    }

    const int br = tid >> 4, bq = tid & 15;
    auto matOf = [&](int i) { return (i == 0) ? 8 : (i - 1); };   // w1 first, then rels
    auto loadB = [&](int mat, int buf) {
#pragma unroll
        for (int seg = 0; seg < 2; ++seg) {
            const bf16* g = (seg ? Wlo : Whi) + (size_t)mat * 16384;
#pragma unroll
            for (int c = 0; c < 4; ++c) {
                cp16z(sB0 + buf * B_BUF + seg * B_SEG + c * B_CHUNK + br * B_STRIDE + bq * 16,
                      g + (size_t)(c * 32 + br) * 128 + bq * 8, 16);
                cp16z(sB0 + buf * B_BUF + seg * B_SEG + c * B_CHUNK + (br + 16) * B_STRIDE + bq * 16,
                      g + (size_t)(c * 32 + br + 16) * 128 + bq * 8, 16);
            }
        }
    };
    loadB(matOf(0), 0);
    cp_commit();

    float acc[4][4][4];
#pragma unroll
    for (int f = 0; f < 4; ++f)
#pragma unroll
        for (int g = 0; g < 4; ++g)
#pragma unroll
            for (int r = 0; r < 4; ++r) acc[f][g][r] = 0.f;

    const int arow = lane & 15, ahalf = lane >> 4;
    const int blrow = lane & 15, bnc = (lane >> 4) * 8;
    const int tr = lane >> 2, tc = (lane & 3) * 2;

    for (int i = 0; i < 9; ++i) {
        const int buf = i & 1;
        cp_wait<0>();
        __syncthreads();
        if (i < 8) { loadB(matOf(i + 1), buf ^ 1); cp_commit(); }

        const uint32_t bB = sB0 + buf * B_BUF;
#pragma unroll
        for (int c = 0; c < 4; ++c) {
#pragma unroll
            for (int s = 0; s < 2; ++s) {
                uint32_t ah[4][4], al[4][4], bh[2][4], bl[2][4];
#pragma unroll
                for (int f = 0; f < 4; ++f) {
                    uint32_t aa = sA0 + c * A_CHUNK + (wm * 64 + f * 16 + arow) * A_STRIDE
                                + (s * 2 + ahalf) * 16;
                    ldsm4(aa,         ah[f][0], ah[f][1], ah[f][2], ah[f][3]);
                    ldsm4(aa + A_SEG, al[f][0], al[f][1], al[f][2], al[f][3]);
                }
#pragma unroll
                for (int g = 0; g < 2; ++g) {
                    uint32_t ba = bB + c * B_CHUNK + (s * 16 + blrow) * B_STRIDE
                                + (wn * 32 + g * 16 + bnc) * 2;
                    ldsm4t(ba,         bh[g][0], bh[g][1], bh[g][2], bh[g][3]);
                    ldsm4t(ba + B_SEG, bl[g][0], bl[g][1], bl[g][2], bl[g][3]);
                }
#pragma unroll
                for (int f = 0; f < 4; ++f) {
#pragma unroll
                    for (int g = 0; g < 2; ++g) {
                        mma16816(acc[f][g*2+0][0], acc[f][g*2+0][1], acc[f][g*2+0][2], acc[f][g*2+0][3],
                                 ah[f][0], ah[f][1], ah[f][2], ah[f][3], bh[g][0], bh[g][1]);
                        mma16816(acc[f][g*2+1][0], acc[f][g*2+1][1], acc[f][g*2+1][2], acc[f][g*2+1][3],
                                 ah[f][0], ah[f][1], ah[f][2], ah[f][3], bh[g][2], bh[g][3]);
                        mma16816(acc[f][g*2+0][0], acc[f][g*2+0][1], acc[f][g*2+0][2], acc[f][g*2+0][3],
                                 ah[f][0], ah[f][1], ah[f][2], ah[f][3], bl[g][0], bl[g][1]);
                        mma16816(acc[f][g*2+1][0], acc[f][g*2+1][1], acc[f][g*2+1][2], acc[f][g*2+1][3],
                                 ah[f][0], ah[f][1], ah[f][2], ah[f][3], bl[g][2], bl[g][3]);
                        mma16816(acc[f][g*2+0][0], acc[f][g*2+0][1], acc[f][g*2+0][2], acc[f][g*2+0][3],
                                 al[f][0], al[f][1], al[f][2], al[f][3], bh[g][0], bh[g][1]);
                        mma16816(acc[f][g*2+1][0], acc[f][g*2+1][1], acc[f][g*2+1][2], acc[f][g*2+1][3],
                                 al[f][0], al[f][1], al[f][2], al[f][3], bh[g][2], bh[g][3]);
                    }
                }
            }
        }

        const int mat = matOf(i);
        float* C = (mat < 8) ? (hall + (size_t)mat * Nn * 128) : b1;
        const bool useBias = (mat == 8);
#pragma unroll
        for (int f = 0; f < 4; ++f) {
            int m0 = row0 + wm * 64 + f * 16 + tr;
            int m1 = m0 + 8;
#pragma unroll
            for (int g = 0; g < 4; ++g) {
                int col = wn * 32 + g * 8 + tc;
                float v00 = acc[f][g][0], v01 = acc[f][g][1];
                float v10 = acc[f][g][2], v11 = acc[f][g][3];
                if (useBias) {
                    float bb0 = w1_b[col], bb1 = w1_b[col + 1];
                    v00 += bb0; v01 += bb1; v10 += bb0; v11 += bb1;
                }
                if (m0 < n_rows) *(float2*)(C + (size_t)m0 * 128 + col) = make_float2(v00, v01);
                if (m1 < n_rows) *(float2*)(C + (size_t)m1 * 128 + col) = make_float2(v10, v11);
                acc[f][g][0] = acc[f][g][1] = acc[f][g][2] = acc[f][g][3] = 0.f;
            }
        }
    }
}

// ================= fused MLP (proven round 7, byte-identical) =================
__global__ __launch_bounds__(256, 1) void mlp_fused(
    const float* __restrict__ B1,
    const bf16* __restrict__ M1hi, const bf16* __restrict__ M1lo,
    const bf16* __restrict__ M2hi, const bf16* __restrict__ M2lo,
    const float* __restrict__ m1_b, const float* __restrict__ m2_b,
    float* __restrict__ out, int n_rows)
{
    extern __shared__ __align__(16) char sm[];
    const uint32_t sStage = s2u(sm);
    const uint32_t sA0 = sStage + 65536;
    const uint32_t sB0 = sA0 + 2 * A_SEG;

    const int tid = threadIdx.x, lane = tid & 31, wid = tid >> 5;
    const int wm = wid & 1, wn = wid >> 1;
    const int row0 = blockIdx.x * 128;

    {
        const int r = tid >> 1, h = tid & 1;
        const int gr = row0 + r;
#pragma unroll
        for (int i = 0; i < 16; ++i)
            cp16z(sStage + r * 512 + h * 256 + i * 16,
                  B1 + (size_t)gr * 128 + h * 64 + i * 4, gr < n_rows ? 16 : 0);
    }
    const int br = tid >> 4, bq = tid & 15;
    auto loadB = [&](const bf16* Bh, const bf16* Bl) {
#pragma unroll
        for (int seg = 0; seg < 2; ++seg) {
            const bf16* g = seg ? Bl : Bh;
#pragma unroll
            for (int c = 0; c < 4; ++c) {
                cp16z(sB0 + seg * B_SEG + c * B_CHUNK + br * B_STRIDE + bq * 16,
                      g + (size_t)(c * 32 + br) * 128 + bq * 8, 16);
                cp16z(sB0 + seg * B_SEG + c * B_CHUNK + (br + 16) * B_STRIDE + bq * 16,
                      g + (size_t)(c * 32 + br + 16) * 128 + bq * 8, 16);
            }
        }
    };
    loadB(M1hi, M1lo);
    cp_commit();
    cp_wait<0>();
    __syncthreads();

    {
        const int r = tid >> 1, h = tid & 1;
#pragma unroll
        for (int j = 0; j < 32; ++j) {
            int col = h * 64 + j * 2;
            float2 v = *(const float2*)(sm + r * 512 + col * 4);
            bf16 h0 = __float2bfloat16(v.x), h1 = __float2bfloat16(v.y);
            uint32_t o = (col >> 5) * A_CHUNK + r * A_STRIDE + (col & 31) * 2;
            *(__nv_bfloat162*)(sm + 65536 + o) = __nv_bfloat162(h0, h1);
            *(__nv_bfloat162*)(sm + 65536 + A_SEG + o) = __nv_bfloat162(
                __float2bfloat16(v.x - __bfloat162float(h0)),
                __float2bfloat16(v.y - __bfloat162float(h1)));
        }
    }
    __syncthreads();

    float acc[4][4][4];
#pragma unroll
    for (int f = 0; f < 4; ++f)
#pragma unroll
        for (int g = 0; g < 4; ++g)
#pragma unroll
            for (int r = 0; r < 4; ++r) acc[f][g][r] = 0.f;

    const int arow = lane & 15, ahalf = lane >> 4;
    const int blrow = lane & 15, bnc = (lane >> 4) * 8;
    const int tr = lane >> 2, tc = (lane & 3) * 2;

    auto mma_pass = [&]() {
#pragma unroll
        for (int c = 0; c < 4; ++c) {
#pragma unroll
            for (int s = 0; s < 2; ++s) {
                uint32_t ah[4][4], al[4][4], bh[2][4], bl[2][4];
#pragma unroll
                for (int f = 0; f < 4; ++f) {
                    uint32_t aa = sA0 + c * A_CHUNK + (wm * 64 + f * 16 + arow) * A_STRIDE
                                + (s * 2 + ahalf) * 16;
                    ldsm4(aa,         ah[f][0], ah[f][1], ah[f][2], ah[f][3]);
                    ldsm4(aa + A_SEG, al[f][0], al[f][1], al[f][2], al[f][3]);
                }
#pragma unroll
                for (int g = 0; g < 2; ++g) {
                    uint32_t ba = sB0 + c * B_CHUNK + (s * 16 + blrow) * B_STRIDE
                                + (wn * 32 + g * 16 + bnc) * 2;
                    ldsm4t(ba,         bh[g][0], bh[g][1], bh[g][2], bh[g][3]);
                    ldsm4t(ba + B_SEG, bl[g][0], bl[g][1], bl[g][2], bl[g][3]);
                }
#pragma unroll
                for (int f = 0; f < 4; ++f) {
#pragma unroll
                    for (int g = 0; g < 2; ++g) {
                        mma16816(acc[f][g*2+0][0], acc[f][g*2+0][1], acc[f][g*2+0][2], acc[f][g*2+0][3],
                                 ah[f][0], ah[f][1], ah[f][2], ah[f][3], bh[g][0], bh[g][1]);
                        mma16816(acc[f][g*2+1][0], acc[f][g*2+1][1], acc[f][g*2+1][2], acc[f][g*2+1][3],
                                 ah[f][0], ah[f][1], ah[f][2], ah[f][3], bh[g][2], bh[g][3]);
                        mma16816(acc[f][g*2+0][0], acc[f][g*2+0][1], acc[f][g*2+0][2], acc[f][g*2+0][3],
                                 ah[f][0], ah[f][1], ah[f][2], ah[f][3], bl[g][0], bl[g][1]);
                        mma16816(acc[f][g*2+1][0], acc[f][g*2+1][1], acc[f][g*2+1][2], acc[f][g*2+1][3],
                                 ah[f][0], ah[f][1], ah[f][2], ah[f][3], bl[g][2], bl[g][3]);
                        mma16816(acc[f][g*2+0][0], acc[f][g*2+0][1], acc[f][g*2+0][2], acc[f][g*2+0][3],
                                 al[f][0], al[f][1], al[f][2], al[f][3], bh[g][0], bh[g][1]);
                        mma16816(acc[f][g*2+1][0], acc[f][g*2+1][1], acc[f][g*2+1][2], acc[f][g*2+1][3],
                                 al[f][0], al[f][1], al[f][2], al[f][3], bh[g][2], bh[g][3]);
                    }
                }
            }
        }
    };

    mma_pass();
    __syncthreads();

    loadB(M2hi, M2lo);
    cp_commit();

#pragma unroll
    for (int f = 0; f < 4; ++f) {
        int r0l = wm * 64 + f * 16 + tr;
        int r1l = r0l + 8;
#pragma unroll
        for (int g = 0; g < 4; ++g) {
            int col = wn * 32 + g * 8 + tc;
            float bb0 = m1_b[col], bb1 = m1_b[col + 1];
            float v00 = fmaxf(acc[f][g][0] + bb0, 0.f);
            float v01 = fmaxf(acc[f][g][1] + bb1, 0.f);
            float v10 = fmaxf(acc[f][g][2] + bb0, 0.f);
            float v11 = fmaxf(acc[f][g][3] + bb1, 0.f);
            uint32_t off0 = (col >> 5) * A_CHUNK + r0l * A_STRIDE + (col & 31) * 2;
            uint32_t off1 = (col >> 5) * A_CHUNK + r1l * A_STRIDE + (col & 31) * 2;
            bf16 h00 = __float2bfloat16(v00), h01 = __float2bfloat16(v01);
            bf16 h10 = __float2bfloat16(v10), h11 = __float2bfloat16(v11);
            *(__nv_bfloat162*)(sm + 65536 + off0) = __nv_bfloat162(h00, h01);
            *(__nv_bfloat162*)(sm + 65536 + off1) = __nv_bfloat162(h10, h11);
            *(__nv_bfloat162*)(sm + 65536 + A_SEG + off0) = __nv_bfloat162(
                __float2bfloat16(v00 - __bfloat162float(h00)),
                __float2bfloat16(v01 - __bfloat162float(h01)));
            *(__nv_bfloat162*)(sm + 65536 + A_SEG + off1) = __nv_bfloat162(
                __float2bfloat16(v10 - __bfloat162float(h10)),
                __float2bfloat16(v11 - __bfloat162float(h11)));
            acc[f][g][0] = acc[f][g][1] = acc[f][g][2] = acc[f][g][3] = 0.f;
        }
    }
    cp_wait<0>();
    __syncthreads();

    mma_pass();

#pragma unroll
    for (int f = 0; f < 4; ++f) {
        int m0 = row0 + wm * 64 + f * 16 + tr;
        int m1 = m0 + 8;
#pragma unroll
        for (int g = 0; g < 4; ++g) {
            int col = wn * 32 + g * 8 + tc;
            float bb0 = m2_b[col], bb1 = m2_b[col + 1];
            if (m0 < n_rows)
                *(float2*)(out + (size_t)m0 * 128 + col) =
                    make_float2(acc[f][g][0] + bb0, acc[f][g][1] + bb1);
            if (m1 < n_rows)
                *(float2*)(out + (size_t)m1 * 128 + col) =
                    make_float2(acc[f][g][2] + bb0, acc[f][g][3] + bb1);
        }
    }
}

// ---------------- merged weight split ----------------
__global__ __launch_bounds__(256) void wsplit_kernel(
    const float4* __restrict__ Wrel, const float4* __restrict__ w1W,
    const float4* __restrict__ m1W,  const float4* __restrict__ m2W,
    __nv_bfloat162* __restrict__ Wchi, __nv_bfloat162* __restrict__ Wclo,
    __nv_bfloat162* __restrict__ m1hi, __nv_bfloat162* __restrict__ m1lo,
    __nv_bfloat162* __restrict__ m2hi, __nv_bfloat162* __restrict__ m2lo)
{
    int i = blockIdx.x * 256 + threadIdx.x;
    if (i >= 11 * 4096) return;
    const int mat = i >> 12, local = i & 4095;
    const float4* in;
    __nv_bfloat162 *hi, *lo;
    if (mat < 8)       { in = Wrel + i;    hi = Wchi + i * 2;                  lo = Wclo + i * 2; }
    else if (mat == 8) { in = w1W + local; hi = Wchi + (8 * 4096 + local) * 2; lo = Wclo + (8 * 4096 + local) * 2; }
    else if (mat == 9) { in = m1W + local; hi = m1hi + local * 2;              lo = m1lo + local * 2; }
    else               { in = m2W + local; hi = m2hi + local * 2;              lo = m2lo + local * 2; }
    float4 v = *in;
    bf16 hx = __float2bfloat16(v.x), hy = __float2bfloat16(v.y);
    bf16 hz = __float2bfloat16(v.z), hw = __float2bfloat16(v.w);
    hi[0] = __nv_bfloat162(hx, hy);
    hi[1] = __nv_bfloat162(hz, hw);
    lo[0] = __nv_bfloat162(__float2bfloat16(v.x - __bfloat162float(hx)),
                           __float2bfloat16(v.y - __bfloat162float(hy)));
    lo[1] = __nv_bfloat162(__float2bfloat16(v.z - __bfloat162float(hz)),
                           __float2bfloat16(v.w - __bfloat162float(hw)));
}

// ---------------- edge scatter: 8 edges per warp ----------------
__global__ __launch_bounds__(256) void edge_scatter(
    const float* __restrict__ hall,
    const int* __restrict__ src, const int* __restrict__ dst,
    const int* __restrict__ etype, float* __restrict__ agg)
{
    const int w    = (blockIdx.x * 256 + threadIdx.x) >> 5;
    const int lane = threadIdx.x & 31;
    const int e0   = w * 8;
    if (e0 >= Ee) return;

    int s[8], d[8], t[8];
#pragma unroll
    for (int i = 0; i < 8; ++i) {
        s[i] = __ldg(src + e0 + i);
        d[i] = __ldg(dst + e0 + i);
        t[i] = __ldg(etype + e0 + i);
    }
    float4 v[8];
#pragma unroll
    for (int i = 0; i < 8; ++i)
        v[i] = ((const float4*)(hall + ((size_t)t[i] * Nn + s[i]) * 128))[lane];
#pragma unroll
    for (int i = 0; i < 8; ++i) {
        float* o = agg + (size_t)d[i] * 128 + lane * 4;
        asm volatile("red.global.add.v4.f32 [%0], {%1,%2,%3,%4};"
                     :: "l"(o), "f"(v[i].x), "f"(v[i].y), "f"(v[i].z), "f"(v[i].w) : "memory");
    }
}

// ---------------- launch ----------------
extern "C" void kernel_launch(void* const* d_in, const int* in_sizes, int n_in,
                              void* d_out, int out_size)
{
    const float* x     = (const float*)d_in[0];
    const int*   src   = (const int*)  d_in[1];
    const int*   dst   = (const int*)  d_in[2];
    const int*   etype = (const int*)  d_in[3];
    const float* W_rel = (const float*)d_in[4];
    const float* w1_W  = (const float*)d_in[5];
    const float* w1_b  = (const float*)d_in[6];
    const float* m1_W  = (const float*)d_in[7];
    const float* m1_b  = (const float*)d_in[8];
    const float* m2_W  = (const float*)d_in[9];
    const float* m2_b  = (const float*)d_in[10];
    float* out = (float*)d_out;

    float *hall, *b1;
    bf16 *Wchi, *Wclo, *m1hi, *m1lo, *m2hi, *m2lo;
    cudaGetSymbolAddress((void**)&hall, g_hall);
    cudaGetSymbolAddress((void**)&b1,   g_b1);
    cudaGetSymbolAddress((void**)&Wchi, g_Wchi);
    cudaGetSymbolAddress((void**)&Wclo, g_Wclo);
    cudaGetSymbolAddress((void**)&m1hi, g_m1hi);
    cudaGetSymbolAddress((void**)&m1lo, g_m1lo);
    cudaGetSymbolAddress((void**)&m2hi, g_m2hi);
    cudaGetSymbolAddress((void**)&m2lo, g_m2lo);

    cudaFuncSetAttribute(rgemm_fused, cudaFuncAttributeMaxDynamicSharedMemorySize, FUSED_SMEM);
    cudaFuncSetAttribute(mlp_fused,   cudaFuncAttributeMaxDynamicSharedMemorySize, MLP_SMEM);

    const int nTiles = (Nn + 127) / 128;  // 391
    const int sgrid  = (Ee + 63) / 64;    // 8 edges/warp, 8 warps/block -> 10000

    wsplit_kernel<<<(11 * 4096 + 255) / 256, 256>>>(
        (const float4*)W_rel, (const float4*)w1_W,
        (const float4*)m1_W, (const float4*)m2_W,
        (__nv_bfloat162*)Wchi, (__nv_bfloat162*)Wclo,
        (__nv_bfloat162*)m1hi, (__nv_bfloat162*)m1lo,
        (__nv_bfloat162*)m2hi, (__nv_bfloat162*)m2lo);

    // hall[r] = x @ W_rel[r]; b1 = x @ w1 + w1_b (w1 computed first)
    rgemm_fused<<<nTiles, 256, FUSED_SMEM>>>(x, Wchi, Wclo, w1_b, hall, b1, Nn);

    // b1[dst] += hall[etype, src]   (8 edges per warp)
    edge_scatter<<<sgrid, 256>>>(hall, src, dst, etype, b1);

    // out = relu(b1 @ m1 + b) @ m2 + b
    mlp_fused<<<nTiles, 256, MLP_SMEM>>>(b1, m1hi, m1lo, m2hi, m2lo,
                                         m1_b, m2_b, out, Nn);
}

// round 12
// speedup vs baseline: 1.2898x; 1.0015x over previous
#include <cuda_runtime.h>
#include <cuda_bf16.h>
#include <cstdint>

#define Nn 50000
#define Ee 640000
#define Rr 8
typedef __nv_bfloat16 bf16;

// ---------------- scratch ----------------
__device__ float g_hall[(size_t)Rr * Nn * 128];
__device__ float g_b1[(size_t)Nn * 128];
__device__ bf16  g_Wchi[9 * 128 * 128], g_Wclo[9 * 128 * 128];   // 8 rels + w1
__device__ bf16  g_m1hi[128 * 128], g_m1lo[128 * 128];
__device__ bf16  g_m2hi[128 * 128], g_m2lo[128 * 128];

// ---------------- asm helpers ----------------
__device__ __forceinline__ uint32_t s2u(const void* p) {
    return (uint32_t)__cvta_generic_to_shared(p);
}
__device__ __forceinline__ void cp16z(uint32_t d, const void* s, int sz) {
    asm volatile("cp.async.cg.shared.global [%0],[%1],16,%2;\n" :: "r"(d), "l"(s), "r"(sz));
}
__device__ __forceinline__ void cp_commit() { asm volatile("cp.async.commit_group;\n"); }
template<int N> __device__ __forceinline__ void cp_wait() {
    asm volatile("cp.async.wait_group %0;\n" :: "n"(N));
}
__device__ __forceinline__ void ldsm4(uint32_t a, uint32_t& r0, uint32_t& r1,
                                      uint32_t& r2, uint32_t& r3) {
    asm volatile("ldmatrix.sync.aligned.m8n8.x4.shared.b16 {%0,%1,%2,%3}, [%4];"
                 : "=r"(r0), "=r"(r1), "=r"(r2), "=r"(r3) : "r"(a));
}
__device__ __forceinline__ void ldsm4t(uint32_t a, uint32_t& r0, uint32_t& r1,
                                       uint32_t& r2, uint32_t& r3) {
    asm volatile("ldmatrix.sync.aligned.m8n8.x4.trans.shared.b16 {%0,%1,%2,%3}, [%4];"
                 : "=r"(r0), "=r"(r1), "=r"(r2), "=r"(r3) : "r"(a));
}
__device__ __forceinline__ void mma16816(float& d0, float& d1, float& d2, float& d3,
                                         uint32_t a0, uint32_t a1, uint32_t a2, uint32_t a3,
                                         uint32_t b0, uint32_t b1) {
    asm volatile(
        "mma.sync.aligned.m16n8k16.row.col.f32.bf16.bf16.f32 "
        "{%0,%1,%2,%3}, {%4,%5,%6,%7}, {%8,%9}, {%0,%1,%2,%3};"
        : "+f"(d0), "+f"(d1), "+f"(d2), "+f"(d3)
        : "r"(a0), "r"(a1), "r"(a2), "r"(a3), "r"(b0), "r"(b1));
}

#define A_STRIDE 80
#define A_CHUNK  (128 * A_STRIDE)   // 10240
#define A_SEG    (4 * A_CHUNK)      // 40960
#define B_STRIDE 272
#define B_CHUNK  (32 * B_STRIDE)    // 8704
#define B_SEG    (4 * B_CHUNK)      // 34816
#define B_BUF    (2 * B_SEG)        // 69632
#define FUSED_SMEM (2 * A_SEG + 2 * B_BUF)            // 221184

// mlp64: 64-row tiles
#define A_CHUNK64 (64 * A_STRIDE)   // 5120
#define A_SEG64   (4 * A_CHUNK64)   // 20480
#define MLP64_SMEM (2 * A_SEG64 + 2 * B_SEG)          // 110592 -> 2 CTAs/SM

// ================= fused relation GEMM (proven; w1 first) =================
__global__ __launch_bounds__(256, 1) void rgemm_fused(
    const float* __restrict__ X,
    const bf16* __restrict__ Whi, const bf16* __restrict__ Wlo,
    const float* __restrict__ w1_b,
    float* __restrict__ hall, float* __restrict__ b1, int n_rows)
{
    extern __shared__ __align__(16) char sm[];
    const uint32_t sA0 = s2u(sm);
    const uint32_t sB0 = sA0 + 2 * A_SEG;

    const int tid = threadIdx.x, lane = tid & 31, wid = tid >> 5;
    const int wm = wid & 1, wn = wid >> 1;
    const int row0 = blockIdx.x * 128;

    // ---- stage fp32 x tile into sB area, split to sA hi/lo ----
    {
        const int r = tid >> 1, h = tid & 1;
        const int gr = row0 + r;
#pragma unroll
        for (int i = 0; i < 16; ++i)
            cp16z(sB0 + r * 512 + h * 256 + i * 16,
                  X + (size_t)gr * 128 + h * 64 + i * 4, gr < n_rows ? 16 : 0);
        cp_commit();
        cp_wait<0>();
        __syncthreads();
#pragma unroll
        for (int j = 0; j < 32; ++j) {
            int col = h * 64 + j * 2;
            float2 v = *(const float2*)(sm + 2 * A_SEG + r * 512 + col * 4);
            bf16 h0 = __float2bfloat16(v.x), h1 = __float2bfloat16(v.y);
            uint32_t o = (col >> 5) * A_CHUNK + r * A_STRIDE + (col & 31) * 2;
            *(__nv_bfloat162*)(sm + o) = __nv_bfloat162(h0, h1);
            *(__nv_bfloat162*)(sm + A_SEG + o) = __nv_bfloat162(
                __float2bfloat16(v.x - __bfloat162float(h0)),
                __float2bfloat16(v.y - __bfloat162float(h1)));
        }
        __syncthreads();
    }

    const int br = tid >> 4, bq = tid & 15;
    auto matOf = [&](int i) { return (i == 0) ? 8 : (i - 1); };
    auto loadB = [&](int mat, int buf) {
#pragma unroll
        for (int seg = 0; seg < 2; ++seg) {
            const bf16* g = (seg ? Wlo : Whi) + (size_t)mat * 16384;
#pragma unroll
            for (int c = 0; c < 4; ++c) {
                cp16z(sB0 + buf * B_BUF + seg * B_SEG + c * B_CHUNK + br * B_STRIDE + bq * 16,
                      g + (size_t)(c * 32 + br) * 128 + bq * 8, 16);
                cp16z(sB0 + buf * B_BUF + seg * B_SEG + c * B_CHUNK + (br + 16) * B_STRIDE + bq * 16,
                      g + (size_t)(c * 32 + br + 16) * 128 + bq * 8, 16);
            }
        }
    };
    loadB(matOf(0), 0);
    cp_commit();

    float acc[4][4][4];
#pragma unroll
    for (int f = 0; f < 4; ++f)
#pragma unroll
        for (int g = 0; g < 4; ++g)
#pragma unroll
            for (int r = 0; r < 4; ++r) acc[f][g][r] = 0.f;

    const int arow = lane & 15, ahalf = lane >> 4;
    const int blrow = lane & 15, bnc = (lane >> 4) * 8;
    const int tr = lane >> 2, tc = (lane & 3) * 2;

    for (int i = 0; i < 9; ++i) {
        const int buf = i & 1;
        cp_wait<0>();
        __syncthreads();
        if (i < 8) { loadB(matOf(i + 1), buf ^ 1); cp_commit(); }

        const uint32_t bB = sB0 + buf * B_BUF;
#pragma unroll
        for (int c = 0; c < 4; ++c) {
#pragma unroll
            for (int s = 0; s < 2; ++s) {
                uint32_t ah[4][4], al[4][4], bh[2][4], bl[2][4];
#pragma unroll
                for (int f = 0; f < 4; ++f) {
                    uint32_t aa = sA0 + c * A_CHUNK + (wm * 64 + f * 16 + arow) * A_STRIDE
                                + (s * 2 + ahalf) * 16;
                    ldsm4(aa,         ah[f][0], ah[f][1], ah[f][2], ah[f][3]);
                    ldsm4(aa + A_SEG, al[f][0], al[f][1], al[f][2], al[f][3]);
                }
#pragma unroll
                for (int g = 0; g < 2; ++g) {
                    uint32_t ba = bB + c * B_CHUNK + (s * 16 + blrow) * B_STRIDE
                                + (wn * 32 + g * 16 + bnc) * 2;
                    ldsm4t(ba,         bh[g][0], bh[g][1], bh[g][2], bh[g][3]);
                    ldsm4t(ba + B_SEG, bl[g][0], bl[g][1], bl[g][2], bl[g][3]);
                }
#pragma unroll
                for (int f = 0; f < 4; ++f) {
#pragma unroll
                    for (int g = 0; g < 2; ++g) {
                        mma16816(acc[f][g*2+0][0], acc[f][g*2+0][1], acc[f][g*2+0][2], acc[f][g*2+0][3],
                                 ah[f][0], ah[f][1], ah[f][2], ah[f][3], bh[g][0], bh[g][1]);
                        mma16816(acc[f][g*2+1][0], acc[f][g*2+1][1], acc[f][g*2+1][2], acc[f][g*2+1][3],
                                 ah[f][0], ah[f][1], ah[f][2], ah[f][3], bh[g][2], bh[g][3]);
                        mma16816(acc[f][g*2+0][0], acc[f][g*2+0][1], acc[f][g*2+0][2], acc[f][g*2+0][3],
                                 ah[f][0], ah[f][1], ah[f][2], ah[f][3], bl[g][0], bl[g][1]);
                        mma16816(acc[f][g*2+1][0], acc[f][g*2+1][1], acc[f][g*2+1][2], acc[f][g*2+1][3],
                                 ah[f][0], ah[f][1], ah[f][2], ah[f][3], bl[g][2], bl[g][3]);
                        mma16816(acc[f][g*2+0][0], acc[f][g*2+0][1], acc[f][g*2+0][2], acc[f][g*2+0][3],
                                 al[f][0], al[f][1], al[f][2], al[f][3], bh[g][0], bh[g][1]);
                        mma16816(acc[f][g*2+1][0], acc[f][g*2+1][1], acc[f][g*2+1][2], acc[f][g*2+1][3],
                                 al[f][0], al[f][1], al[f][2], al[f][3], bh[g][2], bh[g][3]);
                    }
                }
            }
        }

        const int mat = matOf(i);
        float* C = (mat < 8) ? (hall + (size_t)mat * Nn * 128) : b1;
        const bool useBias = (mat == 8);
#pragma unroll
        for (int f = 0; f < 4; ++f) {
            int m0 = row0 + wm * 64 + f * 16 + tr;
            int m1 = m0 + 8;
#pragma unroll
            for (int g = 0; g < 4; ++g) {
                int col = wn * 32 + g * 8 + tc;
                float v00 = acc[f][g][0], v01 = acc[f][g][1];
                float v10 = acc[f][g][2], v11 = acc[f][g][3];
                if (useBias) {
                    float bb0 = w1_b[col], bb1 = w1_b[col + 1];
                    v00 += bb0; v01 += bb1; v10 += bb0; v11 += bb1;
                }
                if (m0 < n_rows) *(float2*)(C + (size_t)m0 * 128 + col) = make_float2(v00, v01);
                if (m1 < n_rows) *(float2*)(C + (size_t)m1 * 128 + col) = make_float2(v10, v11);
                acc[f][g][0] = acc[f][g][1] = acc[f][g][2] = acc[f][g][3] = 0.f;
            }
        }
    }
}

// ================= fused MLP, 64-row tiles, 2 CTAs/SM =================
__global__ __launch_bounds__(256, 2) void mlp_fused64(
    const float* __restrict__ B1,
    const bf16* __restrict__ M1hi, const bf16* __restrict__ M1lo,
    const bf16* __restrict__ M2hi, const bf16* __restrict__ M2lo,
    const float* __restrict__ m1_b, const float* __restrict__ m2_b,
    float* __restrict__ out, int n_rows)
{
    extern __shared__ __align__(16) char sm[];
    const uint32_t sA0 = s2u(sm);
    const uint32_t sB0 = sA0 + 2 * A_SEG64;

    const int tid = threadIdx.x, lane = tid & 31, wid = tid >> 5;
    const int wm = wid & 1, wn = wid >> 1;
    const int row0 = blockIdx.x * 64;

    const int br = tid >> 4, bq = tid & 15;
    auto loadB = [&](const bf16* Bh, const bf16* Bl) {
#pragma unroll
        for (int seg = 0; seg < 2; ++seg) {
            const bf16* g = seg ? Bl : Bh;
#pragma unroll
            for (int c = 0; c < 4; ++c) {
                cp16z(sB0 + seg * B_SEG + c * B_CHUNK + br * B_STRIDE + bq * 16,
                      g + (size_t)(c * 32 + br) * 128 + bq * 8, 16);
                cp16z(sB0 + seg * B_SEG + c * B_CHUNK + (br + 16) * B_STRIDE + bq * 16,
                      g + (size_t)(c * 32 + br + 16) * 128 + bq * 8, 16);
            }
        }
    };
    loadB(M1hi, M1lo);
    cp_commit();

    // ---- split b1 tile directly from global: 4 threads/row, 32 cols each ----
    {
        const int r = tid >> 2;               // 0..63
        const int c0 = (tid & 3) * 32;
        const int gr = row0 + r;
        const bool ok = gr < n_rows;
#pragma unroll
        for (int j = 0; j < 16; ++j) {
            int col = c0 + j * 2;
            float2 v = ok ? *(const float2*)(B1 + (size_t)gr * 128 + col)
                          : make_float2(0.f, 0.f);
            bf16 h0 = __float2bfloat16(v.x), h1 = __float2bfloat16(v.y);
            uint32_t o = (col >> 5) * A_CHUNK64 + r * A_STRIDE + (col & 31) * 2;
            *(__nv_bfloat162*)(sm + o) = __nv_bfloat162(h0, h1);
            *(__nv_bfloat162*)(sm + A_SEG64 + o) = __nv_bfloat162(
                __float2bfloat16(v.x - __bfloat162float(h0)),
                __float2bfloat16(v.y - __bfloat162float(h1)));
        }
    }
    cp_wait<0>();
    __syncthreads();

    float acc[2][4][4];
#pragma unroll
    for (int f = 0; f < 2; ++f)
#pragma unroll
        for (int g = 0; g < 4; ++g)
#pragma unroll
            for (int r = 0; r < 4; ++r) acc[f][g][r] = 0.f;

    const int arow = lane & 15, ahalf = lane >> 4;
    const int blrow = lane & 15, bnc = (lane >> 4) * 8;
    const int tr = lane >> 2, tc = (lane & 3) * 2;

    auto mma_pass = [&]() {
#pragma unroll
        for (int c = 0; c < 4; ++c) {
#pragma unroll
            for (int s = 0; s < 2; ++s) {
                uint32_t ah[2][4], al[2][4], bh[2][4], bl[2][4];
#pragma unroll
                for (int f = 0; f < 2; ++f) {
                    uint32_t aa = sA0 + c * A_CHUNK64 + (wm * 32 + f * 16 + arow) * A_STRIDE
                                + (s * 2 + ahalf) * 16;
                    ldsm4(aa,           ah[f][0], ah[f][1], ah[f][2], ah[f][3]);
                    ldsm4(aa + A_SEG64, al[f][0], al[f][1], al[f][2], al[f][3]);
                }
#pragma unroll
                for (int g = 0; g < 2; ++g) {
                    uint32_t ba = sB0 + c * B_CHUNK + (s * 16 + blrow) * B_STRIDE
                                + (wn * 32 + g * 16 + bnc) * 2;
                    ldsm4t(ba,         bh[g][0], bh[g][1], bh[g][2], bh[g][3]);
                    ldsm4t(ba + B_SEG, bl[g][0], bl[g][1], bl[g][2], bl[g][3]);
                }
#pragma unroll
                for (int f = 0; f < 2; ++f) {
#pragma unroll
                    for (int g = 0; g < 2; ++g) {
                        mma16816(acc[f][g*2+0][0], acc[f][g*2+0][1], acc[f][g*2+0][2], acc[f][g*2+0][3],
                                 ah[f][0], ah[f][1], ah[f][2], ah[f][3], bh[g][0], bh[g][1]);
                        mma16816(acc[f][g*2+1][0], acc[f][g*2+1][1], acc[f][g*2+1][2], acc[f][g*2+1][3],
                                 ah[f][0], ah[f][1], ah[f][2], ah[f][3], bh[g][2], bh[g][3]);
                        mma16816(acc[f][g*2+0][0], acc[f][g*2+0][1], acc[f][g*2+0][2], acc[f][g*2+0][3],
                                 ah[f][0], ah[f][1], ah[f][2], ah[f][3], bl[g][0], bl[g][1]);
                        mma16816(acc[f][g*2+1][0], acc[f][g*2+1][1], acc[f][g*2+1][2], acc[f][g*2+1][3],
                                 ah[f][0], ah[f][1], ah[f][2], ah[f][3], bl[g][2], bl[g][3]);
                        mma16816(acc[f][g*2+0][0], acc[f][g*2+0][1], acc[f][g*2+0][2], acc[f][g*2+0][3],
                                 al[f][0], al[f][1], al[f][2], al[f][3], bh[g][0], bh[g][1]);
                        mma16816(acc[f][g*2+1][0], acc[f][g*2+1][1], acc[f][g*2+1][2], acc[f][g*2+1][3],
                                 al[f][0], al[f][1], al[f][2], al[f][3], bh[g][2], bh[g][3]);
                    }
                }
            }
        }
    };

    // ---- GEMM 1: b1 @ m1 ----
    mma_pass();
    __syncthreads();

    // prefetch m2 into B buffer (just consumed)
    loadB(M2hi, M2lo);
    cp_commit();

    // bias + relu + split -> sA (b2 tile)
#pragma unroll
    for (int f = 0; f < 2; ++f) {
        int r0l = wm * 32 + f * 16 + tr;
        int r1l = r0l + 8;
#pragma unroll
        for (int g = 0; g < 4; ++g) {
            int col = wn * 32 + g * 8 + tc;
            float bb0 = m1_b[col], bb1 = m1_b[col + 1];
            float v00 = fmaxf(acc[f][g][0] + bb0, 0.f);
            float v01 = fmaxf(acc[f][g][1] + bb1, 0.f);
            float v10 = fmaxf(acc[f][g][2] + bb0, 0.f);
            float v11 = fmaxf(acc[f][g][3] + bb1, 0.f);
            uint32_t off0 = (col >> 5) * A_CHUNK64 + r0l * A_STRIDE + (col & 31) * 2;
            uint32_t off1 = (col >> 5) * A_CHUNK64 + r1l * A_STRIDE + (col & 31) * 2;
            bf16 h00 = __float2bfloat16(v00), h01 = __float2bfloat16(v01);
            bf16 h10 = __float2bfloat16(v10), h11 = __float2bfloat16(v11);
            *(__nv_bfloat162*)(sm + off0) = __nv_bfloat162(h00, h01);
            *(__nv_bfloat162*)(sm + off1) = __nv_bfloat162(h10, h11);
            *(__nv_bfloat162*)(sm + A_SEG64 + off0) = __nv_bfloat162(
                __float2bfloat16(v00 - __bfloat162float(h00)),
                __float2bfloat16(v01 - __bfloat162float(h01)));
            *(__nv_bfloat162*)(sm + A_SEG64 + off1) = __nv_bfloat162(
                __float2bfloat16(v10 - __bfloat162float(h10)),
                __float2bfloat16(v11 - __bfloat162float(h11)));
            acc[f][g][0] = acc[f][g][1] = acc[f][g][2] = acc[f][g][3] = 0.f;
        }
    }
    cp_wait<0>();
    __syncthreads();

    // ---- GEMM 2: b2 @ m2 ----
    mma_pass();

    // ---- final epilogue ----
#pragma unroll
    for (int f = 0; f < 2; ++f) {
        int m0 = row0 + wm * 32 + f * 16 + tr;
        int m1 = m0 + 8;
#pragma unroll
        for (int g = 0; g < 4; ++g) {
            int col = wn * 32 + g * 8 + tc;
            float bb0 = m2_b[col], bb1 = m2_b[col + 1];
            if (m0 < n_rows)
                *(float2*)(out + (size_t)m0 * 128 + col) =
                    make_float2(acc[f][g][0] + bb0, acc[f][g][1] + bb1);
            if (m1 < n_rows)
                *(float2*)(out + (size_t)m1 * 128 + col) =
                    make_float2(acc[f][g][2] + bb0, acc[f][g][3] + bb1);
        }
    }
}

// ---------------- merged weight split ----------------
__global__ __launch_bounds__(256) void wsplit_kernel(
    const float4* __restrict__ Wrel, const float4* __restrict__ w1W,
    const float4* __restrict__ m1W,  const float4* __restrict__ m2W,
    __nv_bfloat162* __restrict__ Wchi, __nv_bfloat162* __restrict__ Wclo,
    __nv_bfloat162* __restrict__ m1hi, __nv_bfloat162* __restrict__ m1lo,
    __nv_bfloat162* __restrict__ m2hi, __nv_bfloat162* __restrict__ m2lo)
{
    int i = blockIdx.x * 256 + threadIdx.x;
    if (i >= 11 * 4096) return;
    const int mat = i >> 12, local = i & 4095;
    const float4* in;
    __nv_bfloat162 *hi, *lo;
    if (mat < 8)       { in = Wrel + i;    hi = Wchi + i * 2;                  lo = Wclo + i * 2; }
    else if (mat == 8) { in = w1W + local; hi = Wchi + (8 * 4096 + local) * 2; lo = Wclo + (8 * 4096 + local) * 2; }
    else if (mat == 9) { in = m1W + local; hi = m1hi + local * 2;              lo = m1lo + local * 2; }
    else               { in = m2W + local; hi = m2hi + local * 2;              lo = m2lo + local * 2; }
    float4 v = *in;
    bf16 hx = __float2bfloat16(v.x), hy = __float2bfloat16(v.y);
    bf16 hz = __float2bfloat16(v.z), hw = __float2bfloat16(v.w);
    hi[0] = __nv_bfloat162(hx, hy);
    hi[1] = __nv_bfloat162(hz, hw);
    lo[0] = __nv_bfloat162(__float2bfloat16(v.x - __bfloat162float(hx)),
                           __float2bfloat16(v.y - __bfloat162float(hy)));
    lo[1] = __nv_bfloat162(__float2bfloat16(v.z - __bfloat162float(hz)),
                           __float2bfloat16(v.w - __bfloat162float(hw)));
}

// ---------------- edge scatter: 4 edges per warp (round-7 proven) ----------------
__global__ __launch_bounds__(256) void edge_scatter(
    const float* __restrict__ hall,
    const int* __restrict__ src, const int* __restrict__ dst,
    const int* __restrict__ etype, float* __restrict__ agg)
{
    const int w    = (blockIdx.x * 256 + threadIdx.x) >> 5;
    const int lane = threadIdx.x & 31;
    const int e0   = w * 4;
    if (e0 >= Ee) return;

    int s[4], d[4], t[4];
#pragma unroll
    for (int i = 0; i < 4; ++i) {
        s[i] = __ldg(src + e0 + i);
        d[i] = __ldg(dst + e0 + i);
        t[i] = __ldg(etype + e0 + i);
    }
    float4 v[4];
#pragma unroll
    for (int i = 0; i < 4; ++i)
        v[i] = ((const float4*)(hall + ((size_t)t[i] * Nn + s[i]) * 128))[lane];
#pragma unroll
    for (int i = 0; i < 4; ++i) {
        float* o = agg + (size_t)d[i] * 128 + lane * 4;
        asm volatile("red.global.add.v4.f32 [%0], {%1,%2,%3,%4};"
                     :: "l"(o), "f"(v[i].x), "f"(v[i].y), "f"(v[i].z), "f"(v[i].w) : "memory");
    }
}

// ---------------- launch ----------------
extern "C" void kernel_launch(void* const* d_in, const int* in_sizes, int n_in,
                              void* d_out, int out_size)
{
    const float* x     = (const float*)d_in[0];
    const int*   src   = (const int*)  d_in[1];
    const int*   dst   = (const int*)  d_in[2];
    const int*   etype = (const int*)  d_in[3];
    const float* W_rel = (const float*)d_in[4];
    const float* w1_W  = (const float*)d_in[5];
    const float* w1_b  = (const float*)d_in[6];
    const float* m1_W  = (const float*)d_in[7];
    const float* m1_b  = (const float*)d_in[8];
    const float* m2_W  = (const float*)d_in[9];
    const float* m2_b  = (const float*)d_in[10];
    float* out = (float*)d_out;

    float *hall, *b1;
    bf16 *Wchi, *Wclo, *m1hi, *m1lo, *m2hi, *m2lo;
    cudaGetSymbolAddress((void**)&hall, g_hall);
    cudaGetSymbolAddress((void**)&b1,   g_b1);
    cudaGetSymbolAddress((void**)&Wchi, g_Wchi);
    cudaGetSymbolAddress((void**)&Wclo, g_Wclo);
    cudaGetSymbolAddress((void**)&m1hi, g_m1hi);
    cudaGetSymbolAddress((void**)&m1lo, g_m1lo);
    cudaGetSymbolAddress((void**)&m2hi, g_m2hi);
    cudaGetSymbolAddress((void**)&m2lo, g_m2lo);

    cudaFuncSetAttribute(rgemm_fused, cudaFuncAttributeMaxDynamicSharedMemorySize, FUSED_SMEM);
    cudaFuncSetAttribute(mlp_fused64, cudaFuncAttributeMaxDynamicSharedMemorySize, MLP64_SMEM);

    const int nTiles   = (Nn + 127) / 128;  // 391
    const int nTiles64 = (Nn + 63) / 64;    // 782
    const int sgrid    = (Ee + 31) / 32;    // 4 edges/warp, 8 warps/block -> 20000

    wsplit_kernel<<<(11 * 4096 + 255) / 256, 256>>>(
        (const float4*)W_rel, (const float4*)w1_W,
        (const float4*)m1_W, (const float4*)m2_W,
        (__nv_bfloat162*)Wchi, (__nv_bfloat162*)Wclo,
        (__nv_bfloat162*)m1hi, (__nv_bfloat162*)m1lo,
        (__nv_bfloat162*)m2hi, (__nv_bfloat162*)m2lo);

    // hall[r] = x @ W_rel[r]; b1 = x @ w1 + w1_b
    rgemm_fused<<<nTiles, 256, FUSED_SMEM>>>(x, Wchi, Wclo, w1_b, hall, b1, Nn);

    // b1[dst] += hall[etype, src]
    edge_scatter<<<sgrid, 256>>>(hall, src, dst, etype, b1);

    // out = relu(b1 @ m1 + b) @ m2 + b   (64-row tiles, 2 CTAs/SM)
    mlp_fused64<<<nTiles64, 256, MLP64_SMEM>>>(b1, m1hi, m1lo, m2hi, m2lo,
                                               m1_b, m2_b, out, Nn);
}

// round 13
// speedup vs baseline: 1.3593x; 1.0539x over previous
#include <cuda_runtime.h>
#include <cuda_bf16.h>
#include <cuda_fp16.h>
#include <cstdint>

#define Nn 50000
#define Ee 640000
#define Rr 8
typedef __nv_bfloat16 bf16;

// ---------------- scratch ----------------
__device__ __half g_hall[(size_t)Rr * Nn * 128];   // fp16 messages (scatter feed)
__device__ float  g_b1[(size_t)Nn * 128];
__device__ bf16   g_Wchi[9 * 128 * 128], g_Wclo[9 * 128 * 128];   // 8 rels + w1
__device__ bf16   g_m1hi[128 * 128], g_m1lo[128 * 128];
__device__ bf16   g_m2hi[128 * 128], g_m2lo[128 * 128];

// ---------------- asm helpers ----------------
__device__ __forceinline__ uint32_t s2u(const void* p) {
    return (uint32_t)__cvta_generic_to_shared(p);
}
__device__ __forceinline__ void cp16z(uint32_t d, const void* s, int sz) {
    asm volatile("cp.async.cg.shared.global [%0],[%1],16,%2;\n" :: "r"(d), "l"(s), "r"(sz));
}
__device__ __forceinline__ void cp_commit() { asm volatile("cp.async.commit_group;\n"); }
template<int N> __device__ __forceinline__ void cp_wait() {
    asm volatile("cp.async.wait_group %0;\n" :: "n"(N));
}
__device__ __forceinline__ void ldsm4(uint32_t a, uint32_t& r0, uint32_t& r1,
                                      uint32_t& r2, uint32_t& r3) {
    asm volatile("ldmatrix.sync.aligned.m8n8.x4.shared.b16 {%0,%1,%2,%3}, [%4];"
                 : "=r"(r0), "=r"(r1), "=r"(r2), "=r"(r3) : "r"(a));
}
__device__ __forceinline__ void ldsm4t(uint32_t a, uint32_t& r0, uint32_t& r1,
                                       uint32_t& r2, uint32_t& r3) {
    asm volatile("ldmatrix.sync.aligned.m8n8.x4.trans.shared.b16 {%0,%1,%2,%3}, [%4];"
                 : "=r"(r0), "=r"(r1), "=r"(r2), "=r"(r3) : "r"(a));
}
__device__ __forceinline__ void mma16816(float& d0, float& d1, float& d2, float& d3,
                                         uint32_t a0, uint32_t a1, uint32_t a2, uint32_t a3,
                                         uint32_t b0, uint32_t b1) {
    asm volatile(
        "mma.sync.aligned.m16n8k16.row.col.f32.bf16.bf16.f32 "
        "{%0,%1,%2,%3}, {%4,%5,%6,%7}, {%8,%9}, {%0,%1,%2,%3};"
        : "+f"(d0), "+f"(d1), "+f"(d2), "+f"(d3)
        : "r"(a0), "r"(a1), "r"(a2), "r"(a3), "r"(b0), "r"(b1));
}

#define A_STRIDE 80
#define A_CHUNK  (128 * A_STRIDE)   // 10240
#define A_SEG    (4 * A_CHUNK)      // 40960
#define B_STRIDE 272
#define B_CHUNK  (32 * B_STRIDE)    // 8704
#define B_SEG    (4 * B_CHUNK)      // 34816
#define B_BUF    (2 * B_SEG)        // 69632
#define FUSED_SMEM (2 * A_SEG + 2 * B_BUF)            // 221184

// mlp64: 64-row tiles
#define A_CHUNK64 (64 * A_STRIDE)   // 5120
#define A_SEG64   (4 * A_CHUNK64)   // 20480
#define MLP64_SMEM (2 * A_SEG64 + 2 * B_SEG)          // 110592 -> 2 CTAs/SM

// ================= fused relation GEMM (proven; w1 first; hall in fp16) =========
__global__ __launch_bounds__(256, 1) void rgemm_fused(
    const float* __restrict__ X,
    const bf16* __restrict__ Whi, const bf16* __restrict__ Wlo,
    const float* __restrict__ w1_b,
    __half* __restrict__ hall, float* __restrict__ b1, int n_rows)
{
    extern __shared__ __align__(16) char sm[];
    const uint32_t sA0 = s2u(sm);
    const uint32_t sB0 = sA0 + 2 * A_SEG;

    const int tid = threadIdx.x, lane = tid & 31, wid = tid >> 5;
    const int wm = wid & 1, wn = wid >> 1;
    const int row0 = blockIdx.x * 128;

    // ---- stage fp32 x tile into sB area, split to sA hi/lo ----
    {
        const int r = tid >> 1, h = tid & 1;
        const int gr = row0 + r;
#pragma unroll
        for (int i = 0; i < 16; ++i)
            cp16z(sB0 + r * 512 + h * 256 + i * 16,
                  X + (size_t)gr * 128 + h * 64 + i * 4, gr < n_rows ? 16 : 0);
        cp_commit();
        cp_wait<0>();
        __syncthreads();
#pragma unroll
        for (int j = 0; j < 32; ++j) {
            int col = h * 64 + j * 2;
            float2 v = *(const float2*)(sm + 2 * A_SEG + r * 512 + col * 4);
            bf16 h0 = __float2bfloat16(v.x), h1 = __float2bfloat16(v.y);
            uint32_t o = (col >> 5) * A_CHUNK + r * A_STRIDE + (col & 31) * 2;
            *(__nv_bfloat162*)(sm + o) = __nv_bfloat162(h0, h1);
            *(__nv_bfloat162*)(sm + A_SEG + o) = __nv_bfloat162(
                __float2bfloat16(v.x - __bfloat162float(h0)),
                __float2bfloat16(v.y - __bfloat162float(h1)));
        }
        __syncthreads();
    }

    const int br = tid >> 4, bq = tid & 15;
    auto matOf = [&](int i) { return (i == 0) ? 8 : (i - 1); };
    auto loadB = [&](int mat, int buf) {
#pragma unroll
        for (int seg = 0; seg < 2; ++seg) {
            const bf16* g = (seg ? Wlo : Whi) + (size_t)mat * 16384;
#pragma unroll
            for (int c = 0; c < 4; ++c) {
                cp16z(sB0 + buf * B_BUF + seg * B_SEG + c * B_CHUNK + br * B_STRIDE + bq * 16,
                      g + (size_t)(c * 32 + br) * 128 + bq * 8, 16);
                cp16z(sB0 + buf * B_BUF + seg * B_SEG + c * B_CHUNK + (br + 16) * B_STRIDE + bq * 16,
                      g + (size_t)(c * 32 + br + 16) * 128 + bq * 8, 16);
            }
        }
    };
    loadB(matOf(0), 0);
    cp_commit();

    float acc[4][4][4];
#pragma unroll
    for (int f = 0; f < 4; ++f)
#pragma unroll
        for (int g = 0; g < 4; ++g)
#pragma unroll
            for (int r = 0; r < 4; ++r) acc[f][g][r] = 0.f;

    const int arow = lane & 15, ahalf = lane >> 4;
    const int blrow = lane & 15, bnc = (lane >> 4) * 8;
    const int tr = lane >> 2, tc = (lane & 3) * 2;

    for (int i = 0; i < 9; ++i) {
        const int buf = i & 1;
        cp_wait<0>();
        __syncthreads();
        if (i < 8) { loadB(matOf(i + 1), buf ^ 1); cp_commit(); }

        const uint32_t bB = sB0 + buf * B_BUF;
#pragma unroll
        for (int c = 0; c < 4; ++c) {
#pragma unroll
            for (int s = 0; s < 2; ++s) {
                uint32_t ah[4][4], al[4][4], bh[2][4], bl[2][4];
#pragma unroll
                for (int f = 0; f < 4; ++f) {
                    uint32_t aa = sA0 + c * A_CHUNK + (wm * 64 + f * 16 + arow) * A_STRIDE
                                + (s * 2 + ahalf) * 16;
                    ldsm4(aa,         ah[f][0], ah[f][1], ah[f][2], ah[f][3]);
                    ldsm4(aa + A_SEG, al[f][0], al[f][1], al[f][2], al[f][3]);
                }
#pragma unroll
                for (int g = 0; g < 2; ++g) {
                    uint32_t ba = bB + c * B_CHUNK + (s * 16 + blrow) * B_STRIDE
                                + (wn * 32 + g * 16 + bnc) * 2;
                    ldsm4t(ba,         bh[g][0], bh[g][1], bh[g][2], bh[g][3]);
                    ldsm4t(ba + B_SEG, bl[g][0], bl[g][1], bl[g][2], bl[g][3]);
                }
#pragma unroll
                for (int f = 0; f < 4; ++f) {
#pragma unroll
                    for (int g = 0; g < 2; ++g) {
                        mma16816(acc[f][g*2+0][0], acc[f][g*2+0][1], acc[f][g*2+0][2], acc[f][g*2+0][3],
                                 ah[f][0], ah[f][1], ah[f][2], ah[f][3], bh[g][0], bh[g][1]);
                        mma16816(acc[f][g*2+1][0], acc[f][g*2+1][1], acc[f][g*2+1][2], acc[f][g*2+1][3],
                                 ah[f][0], ah[f][1], ah[f][2], ah[f][3], bh[g][2], bh[g][3]);
                        mma16816(acc[f][g*2+0][0], acc[f][g*2+0][1], acc[f][g*2+0][2], acc[f][g*2+0][3],
                                 ah[f][0], ah[f][1], ah[f][2], ah[f][3], bl[g][0], bl[g][1]);
                        mma16816(acc[f][g*2+1][0], acc[f][g*2+1][1], acc[f][g*2+1][2], acc[f][g*2+1][3],
                                 ah[f][0], ah[f][1], ah[f][2], ah[f][3], bl[g][2], bl[g][3]);
                        mma16816(acc[f][g*2+0][0], acc[f][g*2+0][1], acc[f][g*2+0][2], acc[f][g*2+0][3],
                                 al[f][0], al[f][1], al[f][2], al[f][3], bh[g][0], bh[g][1]);
                        mma16816(acc[f][g*2+1][0], acc[f][g*2+1][1], acc[f][g*2+1][2], acc[f][g*2+1][3],
                                 al[f][0], al[f][1], al[f][2], al[f][3], bh[g][2], bh[g][3]);
                    }
                }
            }
        }

        const int mat = matOf(i);
#pragma unroll
        for (int f = 0; f < 4; ++f) {
            int m0 = row0 + wm * 64 + f * 16 + tr;
            int m1 = m0 + 8;
#pragma unroll
            for (int g = 0; g < 4; ++g) {
                int col = wn * 32 + g * 8 + tc;
                if (mat < 8) {
                    __half* C = hall + (size_t)mat * Nn * 128;
                    if (m0 < n_rows)
                        *(__half2*)(C + (size_t)m0 * 128 + col) =
                            __floats2half2_rn(acc[f][g][0], acc[f][g][1]);
                    if (m1 < n_rows)
                        *(__half2*)(C + (size_t)m1 * 128 + col) =
                            __floats2half2_rn(acc[f][g][2], acc[f][g][3]);
                } else {
                    float bb0 = w1_b[col], bb1 = w1_b[col + 1];
                    if (m0 < n_rows) *(float2*)(b1 + (size_t)m0 * 128 + col) =
                        make_float2(acc[f][g][0] + bb0, acc[f][g][1] + bb1);
                    if (m1 < n_rows) *(float2*)(b1 + (size_t)m1 * 128 + col) =
                        make_float2(acc[f][g][2] + bb0, acc[f][g][3] + bb1);
                }
                acc[f][g][0] = acc[f][g][1] = acc[f][g][2] = acc[f][g][3] = 0.f;
            }
        }
    }
}

// ================= fused MLP, 64-row tiles, 2 CTAs/SM (proven R12) =================
__global__ __launch_bounds__(256, 2) void mlp_fused64(
    const float* __restrict__ B1,
    const bf16* __restrict__ M1hi, const bf16* __restrict__ M1lo,
    const bf16* __restrict__ M2hi, const bf16* __restrict__ M2lo,
    const float* __restrict__ m1_b, const float* __restrict__ m2_b,
    float* __restrict__ out, int n_rows)
{
    extern __shared__ __align__(16) char sm[];
    const uint32_t sA0 = s2u(sm);
    const uint32_t sB0 = sA0 + 2 * A_SEG64;

    const int tid = threadIdx.x, lane = tid & 31, wid = tid >> 5;
    const int wm = wid & 1, wn = wid >> 1;
    const int row0 = blockIdx.x * 64;

    const int br = tid >> 4, bq = tid & 15;
    auto loadB = [&](const bf16* Bh, const bf16* Bl) {
#pragma unroll
        for (int seg = 0; seg < 2; ++seg) {
            const bf16* g = seg ? Bl : Bh;
#pragma unroll
            for (int c = 0; c < 4; ++c) {
                cp16z(sB0 + seg * B_SEG + c * B_CHUNK + br * B_STRIDE + bq * 16,
                      g + (size_t)(c * 32 + br) * 128 + bq * 8, 16);
                cp16z(sB0 + seg * B_SEG + c * B_CHUNK + (br + 16) * B_STRIDE + bq * 16,
                      g + (size_t)(c * 32 + br + 16) * 128 + bq * 8, 16);
            }
        }
    };
    loadB(M1hi, M1lo);
    cp_commit();

    // ---- split b1 tile directly from global ----
    {
        const int r = tid >> 2;
        const int c0 = (tid & 3) * 32;
        const int gr = row0 + r;
        const bool ok = gr < n_rows;
#pragma unroll
        for (int j = 0; j < 16; ++j) {
            int col = c0 + j * 2;
            float2 v = ok ? *(const float2*)(B1 + (size_t)gr * 128 + col)
                          : make_float2(0.f, 0.f);
            bf16 h0 = __float2bfloat16(v.x), h1 = __float2bfloat16(v.y);
            uint32_t o = (col >> 5) * A_CHUNK64 + r * A_STRIDE + (col & 31) * 2;
            *(__nv_bfloat162*)(sm + o) = __nv_bfloat162(h0, h1);
            *(__nv_bfloat162*)(sm + A_SEG64 + o) = __nv_bfloat162(
                __float2bfloat16(v.x - __bfloat162float(h0)),
                __float2bfloat16(v.y - __bfloat162float(h1)));
        }
    }
    cp_wait<0>();
    __syncthreads();

    float acc[2][4][4];
#pragma unroll
    for (int f = 0; f < 2; ++f)
#pragma unroll
        for (int g = 0; g < 4; ++g)
#pragma unroll
            for (int r = 0; r < 4; ++r) acc[f][g][r] = 0.f;

    const int arow = lane & 15, ahalf = lane >> 4;
    const int blrow = lane & 15, bnc = (lane >> 4) * 8;
    const int tr = lane >> 2, tc = (lane & 3) * 2;

    auto mma_pass = [&]() {
#pragma unroll
        for (int c = 0; c < 4; ++c) {
#pragma unroll
            for (int s = 0; s < 2; ++s) {
                uint32_t ah[2][4], al[2][4], bh[2][4], bl[2][4];
#pragma unroll
                for (int f = 0; f < 2; ++f) {
                    uint32_t aa = sA0 + c * A_CHUNK64 + (wm * 32 + f * 16 + arow) * A_STRIDE
                                + (s * 2 + ahalf) * 16;
                    ldsm4(aa,           ah[f][0], ah[f][1], ah[f][2], ah[f][3]);
                    ldsm4(aa + A_SEG64, al[f][0], al[f][1], al[f][2], al[f][3]);
                }
#pragma unroll
                for (int g = 0; g < 2; ++g) {
                    uint32_t ba = sB0 + c * B_CHUNK + (s * 16 + blrow) * B_STRIDE
                                + (wn * 32 + g * 16 + bnc) * 2;
                    ldsm4t(ba,         bh[g][0], bh[g][1], bh[g][2], bh[g][3]);
                    ldsm4t(ba + B_SEG, bl[g][0], bl[g][1], bl[g][2], bl[g][3]);
                }
#pragma unroll
                for (int f = 0; f < 2; ++f) {
#pragma unroll
                    for (int g = 0; g < 2; ++g) {
                        mma16816(acc[f][g*2+0][0], acc[f][g*2+0][1], acc[f][g*2+0][2], acc[f][g*2+0][3],
                                 ah[f][0], ah[f][1], ah[f][2], ah[f][3], bh[g][0], bh[g][1]);
                        mma16816(acc[f][g*2+1][0], acc[f][g*2+1][1], acc[f][g*2+1][2], acc[f][g*2+1][3],
                                 ah[f][0], ah[f][1], ah[f][2], ah[f][3], bh[g][2], bh[g][3]);
                        mma16816(acc[f][g*2+0][0], acc[f][g*2+0][1], acc[f][g*2+0][2], acc[f][g*2+0][3],
                                 ah[f][0], ah[f][1], ah[f][2], ah[f][3], bl[g][0], bl[g][1]);
                        mma16816(acc[f][g*2+1][0], acc[f][g*2+1][1], acc[f][g*2+1][2], acc[f][g*2+1][3],
                                 ah[f][0], ah[f][1], ah[f][2], ah[f][3], bl[g][2], bl[g][3]);
                        mma16816(acc[f][g*2+0][0], acc[f][g*2+0][1], acc[f][g*2+0][2], acc[f][g*2+0][3],
                                 al[f][0], al[f][1], al[f][2], al[f][3], bh[g][0], bh[g][1]);
                        mma16816(acc[f][g*2+1][0], acc[f][g*2+1][1], acc[f][g*2+1][2], acc[f][g*2+1][3],
                                 al[f][0], al[f][1], al[f][2], al[f][3], bh[g][2], bh[g][3]);
                    }
                }
            }
        }
    };

    mma_pass();
    __syncthreads();

    loadB(M2hi, M2lo);
    cp_commit();

#pragma unroll
    for (int f = 0; f < 2; ++f) {
        int r0l = wm * 32 + f * 16 + tr;
        int r1l = r0l + 8;
#pragma unroll
        for (int g = 0; g < 4; ++g) {
            int col = wn * 32 + g * 8 + tc;
            float bb0 = m1_b[col], bb1 = m1_b[col + 1];
            float v00 = fmaxf(acc[f][g][0] + bb0, 0.f);
            float v01 = fmaxf(acc[f][g][1] + bb1, 0.f);
            float v10 = fmaxf(acc[f][g][2] + bb0, 0.f);
            float v11 = fmaxf(acc[f][g][3] + bb1, 0.f);
            uint32_t off0 = (col >> 5) * A_CHUNK64 + r0l * A_STRIDE + (col & 31) * 2;
            uint32_t off1 = (col >> 5) * A_CHUNK64 + r1l * A_STRIDE + (col & 31) * 2;
            bf16 h00 = __float2bfloat16(v00), h01 = __float2bfloat16(v01);
            bf16 h10 = __float2bfloat16(v10), h11 = __float2bfloat16(v11);
            *(__nv_bfloat162*)(sm + off0) = __nv_bfloat162(h00, h01);
            *(__nv_bfloat162*)(sm + off1) = __nv_bfloat162(h10, h11);
            *(__nv_bfloat162*)(sm + A_SEG64 + off0) = __nv_bfloat162(
                __float2bfloat16(v00 - __bfloat162float(h00)),
                __float2bfloat16(v01 - __bfloat162float(h01)));
            *(__nv_bfloat162*)(sm + A_SEG64 + off1) = __nv_bfloat162(
                __float2bfloat16(v10 - __bfloat162float(h10)),
                __float2bfloat16(v11 - __bfloat162float(h11)));
            acc[f][g][0] = acc[f][g][1] = acc[f][g][2] = acc[f][g][3] = 0.f;
        }
    }
    cp_wait<0>();
    __syncthreads();

    mma_pass();

#pragma unroll
    for (int f = 0; f < 2; ++f) {
        int m0 = row0 + wm * 32 + f * 16 + tr;
        int m1 = m0 + 8;
#pragma unroll
        for (int g = 0; g < 4; ++g) {
            int col = wn * 32 + g * 8 + tc;
            float bb0 = m2_b[col], bb1 = m2_b[col + 1];
            if (m0 < n_rows)
                *(float2*)(out + (size_t)m0 * 128 + col) =
                    make_float2(acc[f][g][0] + bb0, acc[f][g][1] + bb1);
            if (m1 < n_rows)
                *(float2*)(out + (size_t)m1 * 128 + col) =
                    make_float2(acc[f][g][2] + bb0, acc[f][g][3] + bb1);
        }
    }
}

// ---------------- merged weight split ----------------
__global__ __launch_bounds__(256) void wsplit_kernel(
    const float4* __restrict__ Wrel, const float4* __restrict__ w1W,
    const float4* __restrict__ m1W,  const float4* __restrict__ m2W,
    __nv_bfloat162* __restrict__ Wchi, __nv_bfloat162* __restrict__ Wclo,
    __nv_bfloat162* __restrict__ m1hi, __nv_bfloat162* __restrict__ m1lo,
    __nv_bfloat162* __restrict__ m2hi, __nv_bfloat162* __restrict__ m2lo)
{
    int i = blockIdx.x * 256 + threadIdx.x;
    if (i >= 11 * 4096) return;
    const int mat = i >> 12, local = i & 4095;
    const float4* in;
    __nv_bfloat162 *hi, *lo;
    if (mat < 8)       { in = Wrel + i;    hi = Wchi + i * 2;                  lo = Wclo + i * 2; }
    else if (mat == 8) { in = w1W + local; hi = Wchi + (8 * 4096 + local) * 2; lo = Wclo + (8 * 4096 + local) * 2; }
    else if (mat == 9) { in = m1W + local; hi = m1hi + local * 2;              lo = m1lo + local * 2; }
    else               { in = m2W + local; hi = m2hi + local * 2;              lo = m2lo + local * 2; }
    float4 v = *in;
    bf16 hx = __float2bfloat16(v.x), hy = __float2bfloat16(v.y);
    bf16 hz = __float2bfloat16(v.z), hw = __float2bfloat16(v.w);
    hi[0] = __nv_bfloat162(hx, hy);
    hi[1] = __nv_bfloat162(hz, hw);
    lo[0] = __nv_bfloat162(__float2bfloat16(v.x - __bfloat162float(hx)),
                           __float2bfloat16(v.y - __bfloat162float(hy)));
    lo[1] = __nv_bfloat162(__float2bfloat16(v.z - __bfloat162float(hz)),
                           __float2bfloat16(v.w - __bfloat162float(hw)));
}

// ---------------- edge scatter: 4 edges/warp, fp16 hall reads ----------------
__global__ __launch_bounds__(256) void edge_scatter(
    const __half* __restrict__ hall,
    const int* __restrict__ src, const int* __restrict__ dst,
    const int* __restrict__ etype, float* __restrict__ agg)
{
    const int w    = (blockIdx.x * 256 + threadIdx.x) >> 5;
    const int lane = threadIdx.x & 31;
    const int e0   = w * 4;
    if (e0 >= Ee) return;

    int s[4], d[4], t[4];
#pragma unroll
    for (int i = 0; i < 4; ++i) {
        s[i] = __ldg(src + e0 + i);
        d[i] = __ldg(dst + e0 + i);
        t[i] = __ldg(etype + e0 + i);
    }
    __half2 v[4][2];
#pragma unroll
    for (int i = 0; i < 4; ++i) {
        const __half2* row = (const __half2*)(hall + ((size_t)t[i] * Nn + s[i]) * 128);
        uint2 raw = *(const uint2*)(row + lane * 2);
        v[i][0] = *(__half2*)&raw.x;
        v[i][1] = *(__half2*)&raw.y;
    }
#pragma unroll
    for (int i = 0; i < 4; ++i) {
        float2 a = __half22float2(v[i][0]);
        float2 b = __half22float2(v[i][1]);
        float* o = agg + (size_t)d[i] * 128 + lane * 4;
        asm volatile("red.global.add.v4.f32 [%0], {%1,%2,%3,%4};"
                     :: "l"(o), "f"(a.x), "f"(a.y), "f"(b.x), "f"(b.y) : "memory");
    }
}

// ---------------- launch ----------------
extern "C" void kernel_launch(void* const* d_in, const int* in_sizes, int n_in,
                              void* d_out, int out_size)
{
    const float* x     = (const float*)d_in[0];
    const int*   src   = (const int*)  d_in[1];
    const int*   dst   = (const int*)  d_in[2];
    const int*   etype = (const int*)  d_in[3];
    const float* W_rel = (const float*)d_in[4];
    const float* w1_W  = (const float*)d_in[5];
    const float* w1_b  = (const float*)d_in[6];
    const float* m1_W  = (const float*)d_in[7];
    const float* m1_b  = (const float*)d_in[8];
    const float* m2_W  = (const float*)d_in[9];
    const float* m2_b  = (const float*)d_in[10];
    float* out = (float*)d_out;

    __half* hall;
    float* b1;
    bf16 *Wchi, *Wclo, *m1hi, *m1lo, *m2hi, *m2lo;
    cudaGetSymbolAddress((void**)&hall, g_hall);
    cudaGetSymbolAddress((void**)&b1,   g_b1);
    cudaGetSymbolAddress((void**)&Wchi, g_Wchi);
    cudaGetSymbolAddress((void**)&Wclo, g_Wclo);
    cudaGetSymbolAddress((void**)&m1hi, g_m1hi);
    cudaGetSymbolAddress((void**)&m1lo, g_m1lo);
    cudaGetSymbolAddress((void**)&m2hi, g_m2hi);
    cudaGetSymbolAddress((void**)&m2lo, g_m2lo);

    cudaFuncSetAttribute(rgemm_fused, cudaFuncAttributeMaxDynamicSharedMemorySize, FUSED_SMEM);
    cudaFuncSetAttribute(mlp_fused64, cudaFuncAttributeMaxDynamicSharedMemorySize, MLP64_SMEM);

    const int nTiles   = (Nn + 127) / 128;  // 391
    const int nTiles64 = (Nn + 63) / 64;    // 782
    const int sgrid    = (Ee + 31) / 32;    // 4 edges/warp -> 20000 blocks

    wsplit_kernel<<<(11 * 4096 + 255) / 256, 256>>>(
        (const float4*)W_rel, (const float4*)w1_W,
        (const float4*)m1_W, (const float4*)m2_W,
        (__nv_bfloat162*)Wchi, (__nv_bfloat162*)Wclo,
        (__nv_bfloat162*)m1hi, (__nv_bfloat162*)m1lo,
        (__nv_bfloat162*)m2hi, (__nv_bfloat162*)m2lo);

    // hall[r] = x @ W_rel[r] (fp16); b1 = x @ w1 + w1_b (fp32)
    rgemm_fused<<<nTiles, 256, FUSED_SMEM>>>(x, Wchi, Wclo, w1_b, hall, b1, Nn);

    // b1[dst] += hall[etype, src]
    edge_scatter<<<sgrid, 256>>>(hall, src, dst, etype, b1);

    // out = relu(b1 @ m1 + b) @ m2 + b
    mlp_fused64<<<nTiles64, 256, MLP64_SMEM>>>(b1, m1hi, m1lo, m2hi, m2lo,
                                               m1_b, m2_b, out, Nn);
}